// round 14
// baseline (speedup 1.0000x reference)
#include <cuda_runtime.h>
#include <cuda_bf16.h>
#include <math.h>
#include <stdint.h>

typedef unsigned long long ull;

#define INVT 14.285714285714286f
#define C1E  20.609928f   /* INVT * log2(e) */

#if defined(__CUDA_ARCH_FEAT_SM103_ALL) || defined(__CUDA_ARCH_FEAT_SM100_ALL) || defined(__CUDA_ARCH_SPECIFIC__)
#define USE_TC 1
#else
#define USE_TC 0
#endif

// ---------------- scratch (device globals; no allocation) ----------------
__device__ __align__(256) float g_nfull[4][4096][128];            // f32 (fallback only)
__device__ __align__(256) float g_z[4][8][1024][64];              // f32 (fallback only)
__device__ __align__(256) __nv_bfloat16 g_nb_h[4][4096][128];     // bf16 hi
__device__ __align__(256) __nv_bfloat16 g_nb_l[4][4096][128];     // bf16 lo residual (pos/ortho)
__device__ __align__(256) __nv_bfloat16 g_zb_h[4][8][1024][64];
__device__ __align__(256) __nv_bfloat16 g_zb_l[4][8][1024][64];
__device__ float g_S[4 * 4096];        // temporal row sums (atomic)
__device__ float g_SC[32768];          // contrastive row sums (plain store)
__device__ float g_pos[4 * 4096];      // temporal positives (exact hi+lo)
__device__ float g_posC[32768];        // contrastive positives (exact hi+lo)
__device__ float g_acc;

// ---------------- generic helpers ----------------
__device__ __forceinline__ void fma2(ull &acc, ull a, ull b) {
    asm("fma.rn.f32x2 %0, %1, %2, %0;" : "+l"(acc) : "l"(a), "l"(b));
}
__device__ __forceinline__ float ulo(ull v){ return __uint_as_float((unsigned)v); }
__device__ __forceinline__ float uhi(ull v){ return __uint_as_float((unsigned)(v >> 32)); }

__device__ __forceinline__ float4 bf4(uint2 h, uint2 l) {
    float2 h0 = __bfloat1622float2(*(__nv_bfloat162*)&h.x);
    float2 h1 = __bfloat1622float2(*(__nv_bfloat162*)&h.y);
    float2 l0 = __bfloat1622float2(*(__nv_bfloat162*)&l.x);
    float2 l1 = __bfloat1622float2(*(__nv_bfloat162*)&l.y);
    return make_float4(h0.x + l0.x, h0.y + l0.y, h1.x + l1.x, h1.y + l1.y);
}
__device__ __forceinline__ float2 bf2(unsigned h, unsigned l) {
    float2 fh = __bfloat1622float2(*(__nv_bfloat162*)&h);
    float2 fl = __bfloat1622float2(*(__nv_bfloat162*)&l);
    return make_float2(fh.x + fl.x, fh.y + fl.y);
}

template<int BLK>
__device__ __forceinline__ void block_accum(float v, float scale) {
    static __shared__ float red[BLK/32];
    #pragma unroll
    for (int o = 16; o; o >>= 1) v += __shfl_xor_sync(0xffffffffu, v, o);
    int w = threadIdx.x >> 5;
    if ((threadIdx.x & 31) == 0) red[w] = v;
    __syncthreads();
    if (threadIdx.x < 32) {
        float s = (threadIdx.x < BLK/32) ? red[threadIdx.x] : 0.0f;
        #pragma unroll
        for (int o = 16; o; o >>= 1) s += __shfl_xor_sync(0xffffffffu, s, o);
        if (threadIdx.x == 0) atomicAdd(&g_acc, s * scale);
    }
}

__device__ __forceinline__ uint32_t smem_u32(const void* p) {
    uint32_t a;
    asm("{ .reg .u64 t; cvta.to.shared.u64 t, %1; cvt.u32.u64 %0, t; }" : "=r"(a) : "l"(p));
    return a;
}

#if USE_TC
__device__ __forceinline__ bool elect_one() {
    uint32_t p;
    asm volatile("{ .reg .pred p; elect.sync _|p, 0xFFFFFFFF; selp.b32 %0, 1, 0, p; }" : "=r"(p));
    return p != 0;
}
#define MBARRIER_INIT(addr, cnt) \
    asm volatile("mbarrier.init.shared.b64 [%0], %1;" :: "r"(addr), "r"(cnt) : "memory")
#define MBARRIER_INVAL(addr) \
    asm volatile("mbarrier.inval.shared.b64 [%0];" :: "r"(addr) : "memory")
#define MBARRIER_WAIT_PARITY(addr, par) do { \
    uint32_t _m = (addr), _p = (par), _d; \
    asm volatile("{ .reg .pred p; mbarrier.try_wait.parity.acquire.cta.shared::cta.b64 p, [%1], %2; selp.b32 %0,1,0,p; }" \
        : "=r"(_d) : "r"(_m), "r"(_p) : "memory"); \
    if (!_d) { \
        asm volatile("{ .reg .pred P1; WL_%=: mbarrier.try_wait.parity.acquire.cta.shared::cta.b64 P1, [%0], %1, 0x989680; @P1 bra.uni WD_%=; bra.uni WL_%=; WD_%=: }" \
            :: "r"(_m), "r"(_p) : "memory"); \
    } } while (0)
#define TCGEN05_ALLOC(dst, n) \
    asm volatile("tcgen05.alloc.cta_group::1.sync.aligned.shared::cta.b32 [%0], %1;" :: "r"(dst), "r"(n) : "memory")
#define TCGEN05_RELINQ() \
    asm volatile("tcgen05.relinquish_alloc_permit.cta_group::1.sync.aligned;")
#define TCGEN05_DEALLOC(t, n) \
    asm volatile("tcgen05.dealloc.cta_group::1.sync.aligned.b32 %0, %1;" :: "r"(t), "r"(n))
#define TCGEN05_COMMIT(mbar) \
    asm volatile("tcgen05.commit.cta_group::1.mbarrier::arrive::one.shared::cluster.b64 [%0];" :: "r"(mbar) : "memory")
#define TCGEN05_WAIT_LD()   asm volatile("tcgen05.wait::ld.sync.aligned;" ::: "memory")
#define TCGEN05_FENCE_BEFORE() asm volatile("tcgen05.fence::before_thread_sync;" ::: "memory")
#define TCGEN05_FENCE_AFTER()  asm volatile("tcgen05.fence::after_thread_sync;" ::: "memory")
#define FENCE_PROXY() asm volatile("fence.proxy.async.shared::cta;" ::: "memory")
#define LD32X32(r, addr) \
    asm volatile("tcgen05.ld.sync.aligned.32x32b.x32.b32 " \
        "{%0,%1,%2,%3,%4,%5,%6,%7,%8,%9,%10,%11,%12,%13,%14,%15," \
        "%16,%17,%18,%19,%20,%21,%22,%23,%24,%25,%26,%27,%28,%29,%30,%31}, [%32];" \
        : "=r"((r)[0]),"=r"((r)[1]),"=r"((r)[2]),"=r"((r)[3]),"=r"((r)[4]),"=r"((r)[5]),"=r"((r)[6]),"=r"((r)[7]), \
          "=r"((r)[8]),"=r"((r)[9]),"=r"((r)[10]),"=r"((r)[11]),"=r"((r)[12]),"=r"((r)[13]),"=r"((r)[14]),"=r"((r)[15]), \
          "=r"((r)[16]),"=r"((r)[17]),"=r"((r)[18]),"=r"((r)[19]),"=r"((r)[20]),"=r"((r)[21]),"=r"((r)[22]),"=r"((r)[23]), \
          "=r"((r)[24]),"=r"((r)[25]),"=r"((r)[26]),"=r"((r)[27]),"=r"((r)[28]),"=r"((r)[29]),"=r"((r)[30]),"=r"((r)[31]) \
        : "r"(addr))

__device__ __forceinline__ uint64_t make_desc(uint32_t addr) {
    const uint64_t BASE = (2ull << 61) | (1ull << 46) | (64ull << 32) | (1ull << 16);
    return BASE | ((addr >> 4) & 0x3FFF);
}
#define IDESC_BF16 0x8200490u   // kind::f16, bf16 in, f32 acc, M=128, N=128
__device__ __forceinline__ void mma_bf16(uint32_t d, uint64_t a, uint64_t b, bool en) {
    uint32_t e = en ? 1u : 0u;
    asm volatile("{\n\t.reg .pred p;\n\tsetp.ne.u32 p, %4, 0;\n\t"
        "tcgen05.mma.cta_group::1.kind::f16 [%0], %1, %2, %3, {%5,%5,%5,%5}, p;\n\t}"
        :: "r"(d), "l"(a), "l"(b), "r"(IDESC_BF16), "r"(e), "r"(0u) : "memory");
}

// 128 rows x (NC*128) cols gram; single-term bf16 MMA, compact SMEM (A + 2xB),
// 2 CTAs/SM, hoisted staging offsets, hoisted compare operands. Round-13 data path;
// contrastive result now plain-stored to g_SC (loss deferred to k_fin).
template<int KF, int NC, bool TEMPORAL>
__device__ __forceinline__ void gram_tc(const __nv_bfloat16* __restrict__ bh,
                                        int rowbase, int colbase0, int auxbase) {
    constexpr int KSTEPS = KF / 16;
    constexpr int TB = 128 * KF * 2;
    constexpr int AOFF = 2048;
    constexpr int BOFF = 2048 + TB;
    constexpr int F8 = KF / 8;          // 16B chunks per row
    constexpr int ITER = (128 * F8) / 256;
    extern __shared__ char sm[];
    uint32_t smb = smem_u32(sm);
    int tid = threadIdx.x;
    if (tid == 0) { MBARRIER_INIT(smb + 0, 1); MBARRIER_INIT(smb + 8, 1); }
    if (tid < 32) { TCGEN05_ALLOC(smb + 16, 256); TCGEN05_RELINQ(); }

    int go[ITER], so[ITER];
    #pragma unroll
    for (int s = 0; s < ITER; ++s) {
        int i = tid + s * 256;
        int r = i / F8, kq = i % F8;
        go[s] = (r * KF + kq * 8) * 2;
        int bo = ((r >> 3) + (kq >> 3) * 16) * 1024 + (r & 7) * 128 + (kq & 7) * 16;
        bo ^= (bo >> 3) & 0x70;
        so[s] = bo;
    }
    {
        const char* srcA = (const char*)(bh + (size_t)rowbase * KF);
        const char* srcB = (const char*)(bh + (size_t)colbase0 * KF);
        #pragma unroll
        for (int s = 0; s < ITER; ++s) {
            *(uint4*)(sm + AOFF + so[s]) = *(const uint4*)(srcA + go[s]);
            *(uint4*)(sm + BOFF + so[s]) = *(const uint4*)(srcB + go[s]);
        }
    }
    FENCE_PROXY();
    __syncthreads();
    uint32_t tmem; asm("ld.shared.b32 %0, [%1];" : "=r"(tmem) : "r"(smb + 16));
    uint64_t adh = make_desc(smb + AOFF);

    int half = tid >> 7, w4 = (tid >> 5) & 3, lane = tid & 31;
    int rowloc = w4 * 32 + lane;
    int row = rowbase + rowloc;
    float* Ssh = (float*)(sm + 1024);
    float S = 0.0f;

    auto epi = [&](int cp) {
        MBARRIER_WAIT_PARITY(smb + 8u * (cp & 1), (cp >> 1) & 1);
        TCGEN05_FENCE_AFTER();
        if (TEMPORAL) {
            uint32_t r0[32], r1[32];
            LD32X32(r0, tmem + (uint32_t)(cp & 1) * 128 + half * 64);
            LD32X32(r1, tmem + (uint32_t)(cp & 1) * 128 + half * 64 + 32);
            TCGEN05_WAIT_LD();
            int rj0 = row - (colbase0 + cp * 128 + half * 64);
            int rj1 = rj0 - 32;
            #pragma unroll
            for (int j = 0; j < 32; ++j) {
                float d0 = __uint_as_float(r0[j]);
                float d1 = __uint_as_float(r1[j]);
                float e0, e1;
                asm("ex2.approx.f32 %0, %1;" : "=f"(e0) : "f"(fmaf(d0, C1E, -C1E)));
                asm("ex2.approx.f32 %0, %1;" : "=f"(e1) : "f"(fmaf(d1, C1E, -C1E)));
                if (j != rj0) S += e0;
                if (j != rj1) S += e1;
            }
        } else {
            #pragma unroll
            for (int g = 0; g < 2; ++g) {
                uint32_t r[32];
                LD32X32(r, tmem + (uint32_t)(cp & 1) * 128 + half * 64 + g * 32);
                TCGEN05_WAIT_LD();
                int rj = row - (colbase0 + cp * 128 + half * 64 + g * 32);
                #pragma unroll
                for (int j = 0; j < 32; ++j) {
                    float d = __uint_as_float(r[j]);
                    float e;
                    asm("ex2.approx.f32 %0, %1;" : "=f"(e) : "f"(fmaf(d, C1E, -C1E)));
                    if (j != rj) S += e;
                }
            }
        }
        TCGEN05_FENCE_BEFORE();
    };

    for (int c = 0; c < NC; ++c) {
        if (c) __syncthreads();
        if (tid < 32) {
            TCGEN05_FENCE_AFTER();
            if (elect_one()) {
                uint64_t bdh = make_desc(smb + BOFF + (uint32_t)(c & 1) * TB);
                uint32_t dt = tmem + (uint32_t)(c & 1) * 128;
                #pragma unroll
                for (int k = 0; k < KSTEPS; ++k) {
                    uint64_t off = (KF == 128) ? (uint64_t)((k >> 2) * 1024 + (k & 3) * 2)
                                               : (uint64_t)(k * 2);
                    mma_bf16(dt, adh + off, bdh + off, k > 0);
                }
                TCGEN05_COMMIT(smb + 8u * (c & 1));
            }
        }
        if (c >= 1) epi(c - 1);
        if (c + 1 < NC) {
            char* dst = sm + BOFF + (uint32_t)((c + 1) & 1) * TB;
            const char* src = (const char*)(bh + (size_t)(colbase0 + (c + 1) * 128) * KF);
            #pragma unroll
            for (int s = 0; s < ITER; ++s)
                *(uint4*)(dst + so[s]) = *(const uint4*)(src + go[s]);
            FENCE_PROXY();
        }
    }
    epi(NC - 1);

    if (TEMPORAL) {
        atomicAdd(&g_S[auxbase + row], S);
    } else {
        __syncthreads();
        if (half) Ssh[rowloc] = S;
        __syncthreads();
        if (!half) g_SC[auxbase + row] = S + Ssh[rowloc];   // loss deferred to k_fin
    }
    __syncthreads();
    if (tid == 0) { MBARRIER_INVAL(smb + 0); MBARRIER_INVAL(smb + 8); }
    if (tid < 32) TCGEN05_DEALLOC(tmem, 256);
}
#endif // USE_TC

// ---------------- pos / ortho work (arch-independent; used as k_gram tail blocks) ----
__device__ void pos_block(int pb) {           // pb in [0,192)
    int warp = threadIdx.x >> 5, lane = threadIdx.x & 31;
    for (int gid = pb * 8 + warp; gid < 49152; gid += 192 * 8) {
        float s;
        if (gid < 16384) {
            int t = gid >> 12, row = gid & 4095;
            int j0 = (row & ~7) + (((row & 7) == 0) ? 1 : 0);
            uint2 xh = ((const uint2*)&g_nb_h[t][row][0])[lane];
            uint2 xl = ((const uint2*)&g_nb_l[t][row][0])[lane];
            uint2 yh = ((const uint2*)&g_nb_h[t][j0][0])[lane];
            uint2 yl = ((const uint2*)&g_nb_l[t][j0][0])[lane];
            float4 x = bf4(xh, xl), y = bf4(yh, yl);
            s = x.x*y.x + x.y*y.y + x.z*y.z + x.w*y.w;
        } else {
            int idx = gid - 16384;
            int call = idx >> 13, p = (idx >> 10) & 7, n = idx & 1023;
            int q = n ^ 512;
            unsigned xh = ((const unsigned*)&g_zb_h[call][p][n][0])[lane];
            unsigned xl = ((const unsigned*)&g_zb_l[call][p][n][0])[lane];
            unsigned yh = ((const unsigned*)&g_zb_h[call][p][q][0])[lane];
            unsigned yl = ((const unsigned*)&g_zb_l[call][p][q][0])[lane];
            float2 a = bf2(xh, xl), bv = bf2(yh, yl);
            s = a.x*bv.x + a.y*bv.y;
        }
        #pragma unroll
        for (int o = 16; o; o >>= 1) s += __shfl_xor_sync(0xffffffffu, s, o);
        if (lane == 0) {
            if (gid < 16384) g_pos[gid] = s;
            else             g_posC[gid - 16384] = s;
        }
    }
}

__device__ void ortho_block(int ob) {         // ob in [0,96)
    const int ca[6] = {0,0,1,1,2,2}, oa[6] = {0,512,0,512,0,512};
    const int cb[6] = {2,3,2,3,3,3}, ob_[6] = {0,0,512,512,0,512};
    int pair = ob >> 4;
    int r = (ob & 15) * 256 + threadIdx.x;
    int n = r >> 3, p = r & 7;
    float s = 0.0f;
    const unsigned* ah = (const unsigned*)(&g_zb_h[ca[pair]][p][n + oa[pair]][0]);
    const unsigned* al = (const unsigned*)(&g_zb_l[ca[pair]][p][n + oa[pair]][0]);
    const unsigned* bh = (const unsigned*)(&g_zb_h[cb[pair]][p][n + ob_[pair]][0]);
    const unsigned* bl = (const unsigned*)(&g_zb_l[cb[pair]][p][n + ob_[pair]][0]);
    #pragma unroll
    for (int k = 0; k < 32; k++) {
        float2 fa = bf2(ah[k], al[k]);
        float2 fb = bf2(bh[k], bl[k]);
        s += fa.x * fb.x + fa.y * fb.y;
    }
    block_accum<256>(fmaxf(s, 0.0f), 1.0f / 4096.0f);
}

// ---------------- fallback gram device functions (compile-only on this target) --------
#if !USE_TC
#define PT 96
#define PC 68
__device__ void gram_fb_temporal(int t, int rc, int cs) {
    extern __shared__ char smc[];
    float* Ash = (float*)smc;
    float* Bsh = (float*)smc + 128 * PT;
    int tid = threadIdx.x, tx = tid & 15, ty = tid >> 4;
    int rowbase = rc * 128, colbase0 = cs * 2048;
    const float* base = &g_nfull[t][0][0];
    for (int i = tid; i < 128 * 32; i += 256) {
        int r = i >> 5, kq = i & 31;
        ((float4*)(Ash + r * PT))[kq] = ((const float4*)(base + (size_t)(rowbase + r) * 128))[kq];
    }
    float s_acc[8];
    #pragma unroll
    for (int i = 0; i < 8; i++) s_acc[i] = 0.0f;
    for (int cc = 0; cc < 16; cc++) {
        int colbase = colbase0 + cc * 128;
        __syncthreads();
        for (int i = tid; i < 128 * 32; i += 256) {
            int c = i >> 5, kq = i & 31;
            ((float4*)(Bsh + c * PT))[kq] = ((const float4*)(base + (size_t)(colbase + c) * 128))[kq];
        }
        __syncthreads();
        ull acc[8][8];
        #pragma unroll
        for (int i = 0; i < 8; i++)
            #pragma unroll
            for (int j = 0; j < 8; j++) acc[i][j] = 0ull;
        #pragma unroll 2
        for (int k4 = 0; k4 < 32; k4++) {
            ulonglong2 af[8], bf[8];
            #pragma unroll
            for (int i = 0; i < 8; i++)
                af[i] = *(const ulonglong2*)(Ash + (ty + 16*i) * PT + 4*k4);
            #pragma unroll
            for (int j = 0; j < 8; j++)
                bf[j] = *(const ulonglong2*)(Bsh + (tx + 16*j) * PT + 4*k4);
            #pragma unroll
            for (int i = 0; i < 8; i++)
                #pragma unroll
                for (int j = 0; j < 8; j++) {
                    fma2(acc[i][j], af[i].x, bf[j].x);
                    fma2(acc[i][j], af[i].y, bf[j].y);
                }
        }
        #pragma unroll
        for (int i = 0; i < 8; i++) {
            int r = rowbase + ty + 16*i;
            #pragma unroll
            for (int j = 0; j < 8; j++) {
                int c = colbase + tx + 16*j;
                float d = ulo(acc[i][j]) + uhi(acc[i][j]);
                float e = __expf((d - 1.0f) * INVT);
                if (c != r) s_acc[i] += e;
            }
        }
    }
    #pragma unroll
    for (int i = 0; i < 8; i++) {
        float v = s_acc[i];
        v += __shfl_xor_sync(0xffffffffu, v, 1);
        v += __shfl_xor_sync(0xffffffffu, v, 2);
        v += __shfl_xor_sync(0xffffffffu, v, 4);
        v += __shfl_xor_sync(0xffffffffu, v, 8);
        if (tx == 0) atomicAdd(&g_S[t * 4096 + rowbase + ty + 16*i], v);
    }
}
__device__ void gram_fb_contr(int call, int p, int rcb) {
    extern __shared__ char smc[];
    float* Ash = (float*)smc;
    float* Bsh = (float*)smc + 128 * PC;
    int tid = threadIdx.x, tx = tid & 15, ty = tid >> 4;
    int rowbase = rcb * 128;
    int auxbase = (call * 8 + p) * 1024;
    const float* base = &g_z[call][p][0][0];
    for (int i = tid; i < 128 * 16; i += 256) {
        int r = i >> 4, kq = i & 15;
        ((float4*)(Ash + r * PC))[kq] = ((const float4*)(base + (size_t)(rowbase + r) * 64))[kq];
    }
    float s_acc[8];
    #pragma unroll
    for (int i = 0; i < 8; i++) s_acc[i] = 0.0f;
    for (int cc = 0; cc < 8; cc++) {
        int colbase = cc * 128;
        __syncthreads();
        for (int i = tid; i < 128 * 16; i += 256) {
            int c = i >> 4, kq = i & 15;
            ((float4*)(Bsh + c * PC))[kq] = ((const float4*)(base + (size_t)(colbase + c) * 64))[kq];
        }
        __syncthreads();
        ull acc[8][8];
        #pragma unroll
        for (int i = 0; i < 8; i++)
            #pragma unroll
            for (int j = 0; j < 8; j++) acc[i][j] = 0ull;
        #pragma unroll 2
        for (int k4 = 0; k4 < 16; k4++) {
            ulonglong2 af[8], bf[8];
            #pragma unroll
            for (int i = 0; i < 8; i++)
                af[i] = *(const ulonglong2*)(Ash + (ty + 16*i) * PC + 4*k4);
            #pragma unroll
            for (int j = 0; j < 8; j++)
                bf[j] = *(const ulonglong2*)(Bsh + (tx + 16*j) * PC + 4*k4);
            #pragma unroll
            for (int i = 0; i < 8; i++)
                #pragma unroll
                for (int j = 0; j < 8; j++) {
                    fma2(acc[i][j], af[i].x, bf[j].x);
                    fma2(acc[i][j], af[i].y, bf[j].y);
                }
        }
        #pragma unroll
        for (int i = 0; i < 8; i++) {
            int r = rowbase + ty + 16*i;
            #pragma unroll
            for (int j = 0; j < 8; j++) {
                int c = colbase + tx + 16*j;
                float d = ulo(acc[i][j]) + uhi(acc[i][j]);
                float e = __expf((d - 1.0f) * INVT);
                if (c != r) s_acc[i] += e;
            }
        }
    }
    #pragma unroll
    for (int i = 0; i < 8; i++) {
        float v = s_acc[i];
        v += __shfl_xor_sync(0xffffffffu, v, 1);
        v += __shfl_xor_sync(0xffffffffu, v, 2);
        v += __shfl_xor_sync(0xffffffffu, v, 4);
        v += __shfl_xor_sync(0xffffffffu, v, 8);
        if (tx == 0) g_SC[auxbase + rowbase + ty + 16*i] = v;
    }
}
#endif // !USE_TC

// ---------------- kernel 1: normalize + scatter (split-bf16) ----------------
__global__ void k_normalize(const float* __restrict__ t0, const float* __restrict__ t1,
                            const float* __restrict__ t2, const float* __restrict__ t3) {
    int gid = blockIdx.x * 256 + threadIdx.x;
    if (gid < 16384) g_S[gid] = 0.0f;
    if (gid == 0) g_acc = 0.0f;
    int warp = threadIdx.x >> 5, lane = threadIdx.x & 31;
    int gr = blockIdx.x * 8 + warp;
    int t = gr >> 12, r = gr & 4095;
    const float* src = (t == 0) ? t0 : (t == 1) ? t1 : (t == 2) ? t2 : t3;
    float4 v = ((const float4*)(src + (size_t)r * 128))[lane];
    float h = v.x*v.x + v.y*v.y + v.z*v.z + v.w*v.w;
    h += __shfl_xor_sync(0xffffffffu, h, 1);
    h += __shfl_xor_sync(0xffffffffu, h, 2);
    h += __shfl_xor_sync(0xffffffffu, h, 4);
    h += __shfl_xor_sync(0xffffffffu, h, 8);
    float full = h + __shfl_xor_sync(0xffffffffu, h, 16);
    float invh = 1.0f / fmaxf(sqrtf(h),    1e-8f);
    float invf = 1.0f / fmaxf(sqrtf(full), 1e-8f);

    float4 fv = make_float4(v.x*invf, v.y*invf, v.z*invf, v.w*invf);
    float4 hv = make_float4(v.x*invh, v.y*invh, v.z*invh, v.w*invh);
#if !USE_TC
    ((float4*)(&g_nfull[t][r][0]))[lane] = fv;
#endif
    __nv_bfloat16 fh[4], fl[4], hh[4], hl[4];
    float* fp = &fv.x; float* hp = &hv.x;
    #pragma unroll
    for (int i = 0; i < 4; i++) {
        fh[i] = __float2bfloat16(fp[i]);
        fl[i] = __float2bfloat16(fp[i] - __bfloat162float(fh[i]));
        hh[i] = __float2bfloat16(hp[i]);
        hl[i] = __float2bfloat16(hp[i] - __bfloat162float(hh[i]));
    }
    ((uint2*)(&g_nb_h[t][r][0]))[lane] = *(uint2*)fh;
    ((uint2*)(&g_nb_l[t][r][0]))[lane] = *(uint2*)fl;
    int n = r >> 3, p = r & 7;
    int call, off;
    if (lane < 16) { call = (t & 1) ? 1 : 0; off = (t >= 2) ? 512 : 0; }
    else           { call = (t < 2) ? 2 : 3; off = (t & 1) ? 512 : 0; }
    int li = (lane & 15);
#if !USE_TC
    ((float4*)(&g_z[call][p][n + off][0]))[li] = hv;
#endif
    ((uint2*)(&g_zb_h[call][p][n + off][0]))[li] = *(uint2*)hh;
    ((uint2*)(&g_zb_l[call][p][n + off][0]))[li] = *(uint2*)hl;
}

// ---------------- kernel 2: MERGED gram + pos + ortho ----------------
// blocks: [0,256) temporal gram, [256,512) contrastive gram,
//         [512,704) positives (grid-stride), [704,800) ortho.
__global__ void __launch_bounds__(256, 2) k_gram() {
    int b = blockIdx.x;
    if (b >= 704)      { ortho_block(b - 704); return; }
    if (b >= 512)      { pos_block(b - 512);   return; }
#if USE_TC
    if (b < 256) {
        int t = b >> 6, rc = (b >> 1) & 31, cs = b & 1;
        gram_tc<128, 16, true>(&g_nb_h[t][0][0], rc * 128, cs * 2048, t * 4096);
    } else {
        int g = (b - 256) >> 3, rcb = (b - 256) & 7;
        gram_tc<64, 8, false>(&g_zb_h[g >> 3][g & 7][0][0], rcb * 128, 0, g * 1024);
    }
#else
    if (b < 256) {
        int t = b >> 6, rc = (b >> 1) & 31, cs = b & 1;
        gram_fb_temporal(t, rc, cs);
    } else {
        int g = (b - 256) >> 3, rcb = (b - 256) & 7;
        gram_fb_contr(g >> 3, g & 7, rcb);
    }
#endif
}

// ---------------- kernel 3: finalize per-row losses (temporal + contrastive) --------
__global__ void k_fin() {
    int gid = blockIdx.x * 256 + threadIdx.x;   // 0..49151
    float v;
    if (gid < 16384) {
        v = (INVT + logf(g_S[gid]) - g_pos[gid] * INVT) * (1.0f / 4096.0f);
    } else {
        int i = gid - 16384;
        v = (INVT + logf(g_SC[i]) - g_posC[i] * INVT) * (1.0f / 8192.0f);
    }
    block_accum<256>(v, 1.0f);
}

// ---------------- kernel 4: finalize ----------------
__global__ void k_final(float* out) { out[0] = g_acc; }

// ---------------- launch ----------------
extern "C" void kernel_launch(void* const* d_in, const int* in_sizes, int n_in,
                              void* d_out, int out_size) {
    (void)in_sizes; (void)n_in; (void)out_size;
    const float* t0 = (const float*)d_in[0];
    const float* t1 = (const float*)d_in[1];
    const float* t2 = (const float*)d_in[2];
    const float* t3 = (const float*)d_in[3];
    const int SMEM_G = 2048 + 3 * 128 * 128 * 2;   // 100352 -> 2 CTAs/SM
    cudaFuncSetAttribute(k_gram, cudaFuncAttributeMaxDynamicSharedMemorySize, SMEM_G);
    k_normalize<<<2048, 256>>>(t0, t1, t2, t3);
    k_gram<<<800, 256, SMEM_G>>>();
    k_fin<<<192, 256>>>();
    k_final<<<1, 1>>>((float*)d_out);
}

// round 15
// speedup vs baseline: 1.0144x; 1.0144x over previous
#include <cuda_runtime.h>
#include <cuda_bf16.h>
#include <math.h>
#include <stdint.h>

typedef unsigned long long ull;

#define INVT 14.285714285714286f
#define C1E  20.609928f   /* INVT * log2(e) */

#if defined(__CUDA_ARCH_FEAT_SM103_ALL) || defined(__CUDA_ARCH_FEAT_SM100_ALL) || defined(__CUDA_ARCH_SPECIFIC__)
#define USE_TC 1
#else
#define USE_TC 0
#endif

// ---------------- scratch (device globals; no allocation) ----------------
__device__ __align__(256) float g_nfull[4][4096][128];            // f32 (fallback only)
__device__ __align__(256) float g_z[4][8][1024][64];              // f32 (fallback only)
__device__ __align__(256) __nv_bfloat16 g_nb_h[4][4096][128];     // bf16 hi
__device__ __align__(256) __nv_bfloat16 g_nb_l[4][4096][128];     // bf16 lo residual (pos/ortho)
__device__ __align__(256) __nv_bfloat16 g_zb_h[4][8][1024][64];
__device__ __align__(256) __nv_bfloat16 g_zb_l[4][8][1024][64];
__device__ float g_S[4 * 4096];
__device__ float g_pos[4 * 4096];      // temporal positives (exact hi+lo)
__device__ float g_posC[32768];        // contrastive positives (exact hi+lo)
__device__ float g_acc;
__device__ unsigned g_cnt;

// ---------------- generic helpers ----------------
__device__ __forceinline__ void fma2(ull &acc, ull a, ull b) {
    asm("fma.rn.f32x2 %0, %1, %2, %0;" : "+l"(acc) : "l"(a), "l"(b));
}
__device__ __forceinline__ float ulo(ull v){ return __uint_as_float((unsigned)v); }
__device__ __forceinline__ float uhi(ull v){ return __uint_as_float((unsigned)(v >> 32)); }

__device__ __forceinline__ float4 bf4(uint2 h, uint2 l) {
    float2 h0 = __bfloat1622float2(*(__nv_bfloat162*)&h.x);
    float2 h1 = __bfloat1622float2(*(__nv_bfloat162*)&h.y);
    float2 l0 = __bfloat1622float2(*(__nv_bfloat162*)&l.x);
    float2 l1 = __bfloat1622float2(*(__nv_bfloat162*)&l.y);
    return make_float4(h0.x + l0.x, h0.y + l0.y, h1.x + l1.x, h1.y + l1.y);
}
__device__ __forceinline__ float2 bf2(unsigned h, unsigned l) {
    float2 fh = __bfloat1622float2(*(__nv_bfloat162*)&h);
    float2 fl = __bfloat1622float2(*(__nv_bfloat162*)&l);
    return make_float2(fh.x + fl.x, fh.y + fl.y);
}

template<int BLK>
__device__ __forceinline__ void block_accum(float v, float scale) {
    static __shared__ float red[BLK/32];
    #pragma unroll
    for (int o = 16; o; o >>= 1) v += __shfl_xor_sync(0xffffffffu, v, o);
    int w = threadIdx.x >> 5;
    if ((threadIdx.x & 31) == 0) red[w] = v;
    __syncthreads();
    if (threadIdx.x < 32) {
        float s = (threadIdx.x < BLK/32) ? red[threadIdx.x] : 0.0f;
        #pragma unroll
        for (int o = 16; o; o >>= 1) s += __shfl_xor_sync(0xffffffffu, s, o);
        if (threadIdx.x == 0) atomicAdd(&g_acc, s * scale);
    }
}

__device__ __forceinline__ uint32_t smem_u32(const void* p) {
    uint32_t a;
    asm("{ .reg .u64 t; cvta.to.shared.u64 t, %1; cvt.u32.u64 %0, t; }" : "=r"(a) : "l"(p));
    return a;
}

#if USE_TC
__device__ __forceinline__ bool elect_one() {
    uint32_t p;
    asm volatile("{ .reg .pred p; elect.sync _|p, 0xFFFFFFFF; selp.b32 %0, 1, 0, p; }" : "=r"(p));
    return p != 0;
}
#define MBARRIER_INIT(addr, cnt) \
    asm volatile("mbarrier.init.shared.b64 [%0], %1;" :: "r"(addr), "r"(cnt) : "memory")
#define MBARRIER_INVAL(addr) \
    asm volatile("mbarrier.inval.shared.b64 [%0];" :: "r"(addr) : "memory")
#define MBARRIER_WAIT_PARITY(addr, par) do { \
    uint32_t _m = (addr), _p = (par), _d; \
    asm volatile("{ .reg .pred p; mbarrier.try_wait.parity.acquire.cta.shared::cta.b64 p, [%1], %2; selp.b32 %0,1,0,p; }" \
        : "=r"(_d) : "r"(_m), "r"(_p) : "memory"); \
    if (!_d) { \
        asm volatile("{ .reg .pred P1; WL_%=: mbarrier.try_wait.parity.acquire.cta.shared::cta.b64 P1, [%0], %1, 0x989680; @P1 bra.uni WD_%=; bra.uni WL_%=; WD_%=: }" \
            :: "r"(_m), "r"(_p) : "memory"); \
    } } while (0)
#define TCGEN05_ALLOC(dst, n) \
    asm volatile("tcgen05.alloc.cta_group::1.sync.aligned.shared::cta.b32 [%0], %1;" :: "r"(dst), "r"(n) : "memory")
#define TCGEN05_RELINQ() \
    asm volatile("tcgen05.relinquish_alloc_permit.cta_group::1.sync.aligned;")
#define TCGEN05_DEALLOC(t, n) \
    asm volatile("tcgen05.dealloc.cta_group::1.sync.aligned.b32 %0, %1;" :: "r"(t), "r"(n))
#define TCGEN05_COMMIT(mbar) \
    asm volatile("tcgen05.commit.cta_group::1.mbarrier::arrive::one.shared::cluster.b64 [%0];" :: "r"(mbar) : "memory")
#define TCGEN05_WAIT_LD()   asm volatile("tcgen05.wait::ld.sync.aligned;" ::: "memory")
#define TCGEN05_FENCE_BEFORE() asm volatile("tcgen05.fence::before_thread_sync;" ::: "memory")
#define TCGEN05_FENCE_AFTER()  asm volatile("tcgen05.fence::after_thread_sync;" ::: "memory")
#define FENCE_PROXY() asm volatile("fence.proxy.async.shared::cta;" ::: "memory")
#define LD32X32(r, addr) \
    asm volatile("tcgen05.ld.sync.aligned.32x32b.x32.b32 " \
        "{%0,%1,%2,%3,%4,%5,%6,%7,%8,%9,%10,%11,%12,%13,%14,%15," \
        "%16,%17,%18,%19,%20,%21,%22,%23,%24,%25,%26,%27,%28,%29,%30,%31}, [%32];" \
        : "=r"((r)[0]),"=r"((r)[1]),"=r"((r)[2]),"=r"((r)[3]),"=r"((r)[4]),"=r"((r)[5]),"=r"((r)[6]),"=r"((r)[7]), \
          "=r"((r)[8]),"=r"((r)[9]),"=r"((r)[10]),"=r"((r)[11]),"=r"((r)[12]),"=r"((r)[13]),"=r"((r)[14]),"=r"((r)[15]), \
          "=r"((r)[16]),"=r"((r)[17]),"=r"((r)[18]),"=r"((r)[19]),"=r"((r)[20]),"=r"((r)[21]),"=r"((r)[22]),"=r"((r)[23]), \
          "=r"((r)[24]),"=r"((r)[25]),"=r"((r)[26]),"=r"((r)[27]),"=r"((r)[28]),"=r"((r)[29]),"=r"((r)[30]),"=r"((r)[31]) \
        : "r"(addr))

__device__ __forceinline__ uint64_t make_desc(uint32_t addr) {
    const uint64_t BASE = (2ull << 61) | (1ull << 46) | (64ull << 32) | (1ull << 16);
    return BASE | ((addr >> 4) & 0x3FFF);
}
#define IDESC_BF16 0x8200490u   // kind::f16, bf16 in, f32 acc, M=128, N=128
__device__ __forceinline__ void mma_bf16(uint32_t d, uint64_t a, uint64_t b, bool en) {
    uint32_t e = en ? 1u : 0u;
    asm volatile("{\n\t.reg .pred p;\n\tsetp.ne.u32 p, %4, 0;\n\t"
        "tcgen05.mma.cta_group::1.kind::f16 [%0], %1, %2, %3, {%5,%5,%5,%5}, p;\n\t}"
        :: "r"(d), "l"(a), "l"(b), "r"(IDESC_BF16), "r"(e), "r"(0u) : "memory");
}

// 128 rows x (NC*128) cols gram + fused NT-Xent; single-term bf16 MMA, compact SMEM
// (A + 2xB tiles), 2 CTAs/SM. Hoisted staging offsets; hoisted compare operands.
// EXACT round-13 code path (65.7us passing).
template<int KF, int NC, bool TEMPORAL>
__device__ __forceinline__ void gram_tc(const __nv_bfloat16* __restrict__ bh,
                                        int rowbase, int colbase0, int auxbase, float scale) {
    constexpr int KSTEPS = KF / 16;
    constexpr int TB = 128 * KF * 2;
    constexpr int AOFF = 2048;
    constexpr int BOFF = 2048 + TB;
    constexpr int F8 = KF / 8;          // 16B chunks per row
    constexpr int ITER = (128 * F8) / 256;
    extern __shared__ char sm[];
    uint32_t smb = smem_u32(sm);
    int tid = threadIdx.x;
    if (tid == 0) { MBARRIER_INIT(smb + 0, 1); MBARRIER_INIT(smb + 8, 1); }
    if (tid < 32) { TCGEN05_ALLOC(smb + 16, 256); TCGEN05_RELINQ(); }

    int go[ITER], so[ITER];
    #pragma unroll
    for (int s = 0; s < ITER; ++s) {
        int i = tid + s * 256;
        int r = i / F8, kq = i % F8;
        go[s] = (r * KF + kq * 8) * 2;
        int bo = ((r >> 3) + (kq >> 3) * 16) * 1024 + (r & 7) * 128 + (kq & 7) * 16;
        bo ^= (bo >> 3) & 0x70;
        so[s] = bo;
    }
    {
        const char* srcA = (const char*)(bh + (size_t)rowbase * KF);
        const char* srcB = (const char*)(bh + (size_t)colbase0 * KF);
        #pragma unroll
        for (int s = 0; s < ITER; ++s) {
            *(uint4*)(sm + AOFF + so[s]) = *(const uint4*)(srcA + go[s]);
            *(uint4*)(sm + BOFF + so[s]) = *(const uint4*)(srcB + go[s]);
        }
    }
    FENCE_PROXY();
    __syncthreads();
    uint32_t tmem; asm("ld.shared.b32 %0, [%1];" : "=r"(tmem) : "r"(smb + 16));
    uint64_t adh = make_desc(smb + AOFF);

    int half = tid >> 7, w4 = (tid >> 5) & 3, lane = tid & 31;
    int rowloc = w4 * 32 + lane;
    int row = rowbase + rowloc;
    float* Ssh = (float*)(sm + 1024);
    float S = 0.0f;

    auto epi = [&](int cp) {
        MBARRIER_WAIT_PARITY(smb + 8u * (cp & 1), (cp >> 1) & 1);
        TCGEN05_FENCE_AFTER();
        if (TEMPORAL) {
            uint32_t r0[32], r1[32];
            LD32X32(r0, tmem + (uint32_t)(cp & 1) * 128 + half * 64);
            LD32X32(r1, tmem + (uint32_t)(cp & 1) * 128 + half * 64 + 32);
            TCGEN05_WAIT_LD();
            int rj0 = row - (colbase0 + cp * 128 + half * 64);
            int rj1 = rj0 - 32;
            #pragma unroll
            for (int j = 0; j < 32; ++j) {
                float d0 = __uint_as_float(r0[j]);
                float d1 = __uint_as_float(r1[j]);
                float e0, e1;
                asm("ex2.approx.f32 %0, %1;" : "=f"(e0) : "f"(fmaf(d0, C1E, -C1E)));
                asm("ex2.approx.f32 %0, %1;" : "=f"(e1) : "f"(fmaf(d1, C1E, -C1E)));
                if (j != rj0) S += e0;
                if (j != rj1) S += e1;
            }
        } else {
            #pragma unroll
            for (int g = 0; g < 2; ++g) {
                uint32_t r[32];
                LD32X32(r, tmem + (uint32_t)(cp & 1) * 128 + half * 64 + g * 32);
                TCGEN05_WAIT_LD();
                int rj = row - (colbase0 + cp * 128 + half * 64 + g * 32);
                #pragma unroll
                for (int j = 0; j < 32; ++j) {
                    float d = __uint_as_float(r[j]);
                    float e;
                    asm("ex2.approx.f32 %0, %1;" : "=f"(e) : "f"(fmaf(d, C1E, -C1E)));
                    if (j != rj) S += e;
                }
            }
        }
        TCGEN05_FENCE_BEFORE();
    };

    for (int c = 0; c < NC; ++c) {
        if (c) __syncthreads();
        if (tid < 32) {
            TCGEN05_FENCE_AFTER();
            if (elect_one()) {
                uint64_t bdh = make_desc(smb + BOFF + (uint32_t)(c & 1) * TB);
                uint32_t dt = tmem + (uint32_t)(c & 1) * 128;
                #pragma unroll
                for (int k = 0; k < KSTEPS; ++k) {
                    uint64_t off = (KF == 128) ? (uint64_t)((k >> 2) * 1024 + (k & 3) * 2)
                                               : (uint64_t)(k * 2);
                    mma_bf16(dt, adh + off, bdh + off, k > 0);
                }
                TCGEN05_COMMIT(smb + 8u * (c & 1));
            }
        }
        if (c >= 1) epi(c - 1);
        if (c + 1 < NC) {
            char* dst = sm + BOFF + (uint32_t)((c + 1) & 1) * TB;
            const char* src = (const char*)(bh + (size_t)(colbase0 + (c + 1) * 128) * KF);
            #pragma unroll
            for (int s = 0; s < ITER; ++s)
                *(uint4*)(dst + so[s]) = *(const uint4*)(src + go[s]);
            FENCE_PROXY();
        }
    }
    epi(NC - 1);

    if (TEMPORAL) {
        atomicAdd(&g_S[auxbase + row], S);
    } else {
        __syncthreads();
        if (half) Ssh[rowloc] = S;
        __syncthreads();
        float loss = 0.0f;
        if (!half) loss = INVT + logf(S + Ssh[rowloc]) - g_posC[auxbase + row] * INVT;
        block_accum<256>(loss, scale);
    }
    __syncthreads();
    if (tid == 0) { MBARRIER_INVAL(smb + 0); MBARRIER_INVAL(smb + 8); }
    if (tid < 32) TCGEN05_DEALLOC(tmem, 256);
}
#endif // USE_TC

// ---------------- fallback gram device functions (compile-only on this target) --------
#if !USE_TC
#define PT 96
#define PC 68
__device__ void gram_fb_temporal(int t, int rc, int cs) {
    extern __shared__ char smc[];
    float* Ash = (float*)smc;
    float* Bsh = (float*)smc + 128 * PT;
    int tid = threadIdx.x, tx = tid & 15, ty = tid >> 4;
    int rowbase = rc * 128, colbase0 = cs * 2048;
    const float* base = &g_nfull[t][0][0];
    for (int i = tid; i < 128 * 32; i += 256) {
        int r = i >> 5, kq = i & 31;
        ((float4*)(Ash + r * PT))[kq] = ((const float4*)(base + (size_t)(rowbase + r) * 128))[kq];
    }
    float s_acc[8];
    #pragma unroll
    for (int i = 0; i < 8; i++) s_acc[i] = 0.0f;
    for (int cc = 0; cc < 16; cc++) {
        int colbase = colbase0 + cc * 128;
        __syncthreads();
        for (int i = tid; i < 128 * 32; i += 256) {
            int c = i >> 5, kq = i & 31;
            ((float4*)(Bsh + c * PT))[kq] = ((const float4*)(base + (size_t)(colbase + c) * 128))[kq];
        }
        __syncthreads();
        ull acc[8][8];
        #pragma unroll
        for (int i = 0; i < 8; i++)
            #pragma unroll
            for (int j = 0; j < 8; j++) acc[i][j] = 0ull;
        #pragma unroll 2
        for (int k4 = 0; k4 < 32; k4++) {
            ulonglong2 af[8], bf[8];
            #pragma unroll
            for (int i = 0; i < 8; i++)
                af[i] = *(const ulonglong2*)(Ash + (ty + 16*i) * PT + 4*k4);
            #pragma unroll
            for (int j = 0; j < 8; j++)
                bf[j] = *(const ulonglong2*)(Bsh + (tx + 16*j) * PT + 4*k4);
            #pragma unroll
            for (int i = 0; i < 8; i++)
                #pragma unroll
                for (int j = 0; j < 8; j++) {
                    fma2(acc[i][j], af[i].x, bf[j].x);
                    fma2(acc[i][j], af[i].y, bf[j].y);
                }
        }
        #pragma unroll
        for (int i = 0; i < 8; i++) {
            int r = rowbase + ty + 16*i;
            #pragma unroll
            for (int j = 0; j < 8; j++) {
                int c = colbase + tx + 16*j;
                float d = ulo(acc[i][j]) + uhi(acc[i][j]);
                float e = __expf((d - 1.0f) * INVT);
                if (c != r) s_acc[i] += e;
            }
        }
    }
    #pragma unroll
    for (int i = 0; i < 8; i++) {
        float v = s_acc[i];
        v += __shfl_xor_sync(0xffffffffu, v, 1);
        v += __shfl_xor_sync(0xffffffffu, v, 2);
        v += __shfl_xor_sync(0xffffffffu, v, 4);
        v += __shfl_xor_sync(0xffffffffu, v, 8);
        if (tx == 0) atomicAdd(&g_S[t * 4096 + rowbase + ty + 16*i], v);
    }
}
__device__ void gram_fb_contr(int call, int p, int rcb) {
    extern __shared__ char smc[];
    float* Ash = (float*)smc;
    float* Bsh = (float*)smc + 128 * PC;
    int tid = threadIdx.x, tx = tid & 15, ty = tid >> 4;
    int rowbase = rcb * 128;
    int auxbase = (call * 8 + p) * 1024;
    const float* base = &g_z[call][p][0][0];
    for (int i = tid; i < 128 * 16; i += 256) {
        int r = i >> 4, kq = i & 15;
        ((float4*)(Ash + r * PC))[kq] = ((const float4*)(base + (size_t)(rowbase + r) * 64))[kq];
    }
    float s_acc[8];
    #pragma unroll
    for (int i = 0; i < 8; i++) s_acc[i] = 0.0f;
    for (int cc = 0; cc < 8; cc++) {
        int colbase = cc * 128;
        __syncthreads();
        for (int i = tid; i < 128 * 16; i += 256) {
            int c = i >> 4, kq = i & 15;
            ((float4*)(Bsh + c * PC))[kq] = ((const float4*)(base + (size_t)(colbase + c) * 64))[kq];
        }
        __syncthreads();
        ull acc[8][8];
        #pragma unroll
        for (int i = 0; i < 8; i++)
            #pragma unroll
            for (int j = 0; j < 8; j++) acc[i][j] = 0ull;
        #pragma unroll 2
        for (int k4 = 0; k4 < 16; k4++) {
            ulonglong2 af[8], bf[8];
            #pragma unroll
            for (int i = 0; i < 8; i++)
                af[i] = *(const ulonglong2*)(Ash + (ty + 16*i) * PC + 4*k4);
            #pragma unroll
            for (int j = 0; j < 8; j++)
                bf[j] = *(const ulonglong2*)(Bsh + (tx + 16*j) * PC + 4*k4);
            #pragma unroll
            for (int i = 0; i < 8; i++)
                #pragma unroll
                for (int j = 0; j < 8; j++) {
                    fma2(acc[i][j], af[i].x, bf[j].x);
                    fma2(acc[i][j], af[i].y, bf[j].y);
                }
        }
        #pragma unroll
        for (int i = 0; i < 8; i++) {
            int r = rowbase + ty + 16*i;
            #pragma unroll
            for (int j = 0; j < 8; j++) {
                int c = colbase + tx + 16*j;
                float d = ulo(acc[i][j]) + uhi(acc[i][j]);
                float e = __expf((d - 1.0f) * INVT);
                if (c != r) s_acc[i] += e;
            }
        }
    }
    __syncthreads();
    float loss = 0.0f;
    #pragma unroll
    for (int i = 0; i < 8; i++) {
        float v = s_acc[i];
        v += __shfl_xor_sync(0xffffffffu, v, 1);
        v += __shfl_xor_sync(0xffffffffu, v, 2);
        v += __shfl_xor_sync(0xffffffffu, v, 4);
        v += __shfl_xor_sync(0xffffffffu, v, 8);
        if (tx == 0) loss += INVT + logf(v) - g_posC[auxbase + rowbase + ty + 16*i] * INVT;
    }
    block_accum<256>(loss, 1.0f / 8192.0f);
}
#endif // !USE_TC

// ---------------- kernel 1: normalize + scatter (split-bf16) ----------------
__global__ void k_normalize(const float* __restrict__ t0, const float* __restrict__ t1,
                            const float* __restrict__ t2, const float* __restrict__ t3) {
    int gid = blockIdx.x * 256 + threadIdx.x;
    if (gid < 16384) g_S[gid] = 0.0f;
    if (gid == 0) { g_acc = 0.0f; g_cnt = 0u; }
    int warp = threadIdx.x >> 5, lane = threadIdx.x & 31;
    int gr = blockIdx.x * 8 + warp;
    int t = gr >> 12, r = gr & 4095;
    const float* src = (t == 0) ? t0 : (t == 1) ? t1 : (t == 2) ? t2 : t3;
    float4 v = ((const float4*)(src + (size_t)r * 128))[lane];
    float h = v.x*v.x + v.y*v.y + v.z*v.z + v.w*v.w;
    h += __shfl_xor_sync(0xffffffffu, h, 1);
    h += __shfl_xor_sync(0xffffffffu, h, 2);
    h += __shfl_xor_sync(0xffffffffu, h, 4);
    h += __shfl_xor_sync(0xffffffffu, h, 8);
    float full = h + __shfl_xor_sync(0xffffffffu, h, 16);
    float invh = 1.0f / fmaxf(sqrtf(h),    1e-8f);
    float invf = 1.0f / fmaxf(sqrtf(full), 1e-8f);

    float4 fv = make_float4(v.x*invf, v.y*invf, v.z*invf, v.w*invf);
    float4 hv = make_float4(v.x*invh, v.y*invh, v.z*invh, v.w*invh);
#if !USE_TC
    ((float4*)(&g_nfull[t][r][0]))[lane] = fv;
#endif
    __nv_bfloat16 fh[4], fl[4], hh[4], hl[4];
    float* fp = &fv.x; float* hp = &hv.x;
    #pragma unroll
    for (int i = 0; i < 4; i++) {
        fh[i] = __float2bfloat16(fp[i]);
        fl[i] = __float2bfloat16(fp[i] - __bfloat162float(fh[i]));
        hh[i] = __float2bfloat16(hp[i]);
        hl[i] = __float2bfloat16(hp[i] - __bfloat162float(hh[i]));
    }
    ((uint2*)(&g_nb_h[t][r][0]))[lane] = *(uint2*)fh;
    ((uint2*)(&g_nb_l[t][r][0]))[lane] = *(uint2*)fl;
    int n = r >> 3, p = r & 7;
    int call, off;
    if (lane < 16) { call = (t & 1) ? 1 : 0; off = (t >= 2) ? 512 : 0; }
    else           { call = (t < 2) ? 2 : 3; off = (t & 1) ? 512 : 0; }
    int li = (lane & 15);
#if !USE_TC
    ((float4*)(&g_z[call][p][n + off][0]))[li] = hv;
#endif
    ((uint2*)(&g_zb_h[call][p][n + off][0]))[li] = *(uint2*)hh;
    ((uint2*)(&g_zb_l[call][p][n + off][0]))[li] = *(uint2*)hl;
}

// ---------------- kernel 1b: exact positives + ortho (merged; r8-proven pattern) ------
__global__ void k_pos() {
    int b = blockIdx.x;
    if (b >= 6144) {   // ---- ortho blocks ----
        const int ca[6] = {0,0,1,1,2,2}, oa[6] = {0,512,0,512,0,512};
        const int cb[6] = {2,3,2,3,3,3}, ob[6] = {0,0,512,512,0,512};
        int bb = b - 6144;
        int pair = bb >> 4;
        int r = (bb & 15) * 256 + threadIdx.x;
        int n = r >> 3, p = r & 7;
        float s = 0.0f;
        const unsigned* ah = (const unsigned*)(&g_zb_h[ca[pair]][p][n + oa[pair]][0]);
        const unsigned* al = (const unsigned*)(&g_zb_l[ca[pair]][p][n + oa[pair]][0]);
        const unsigned* bh = (const unsigned*)(&g_zb_h[cb[pair]][p][n + ob[pair]][0]);
        const unsigned* bl = (const unsigned*)(&g_zb_l[cb[pair]][p][n + ob[pair]][0]);
        #pragma unroll
        for (int k = 0; k < 32; k++) {
            float2 fa = bf2(ah[k], al[k]);
            float2 fb = bf2(bh[k], bl[k]);
            s += fa.x * fb.x + fa.y * fb.y;
        }
        block_accum<256>(fmaxf(s, 0.0f), 1.0f / 4096.0f);
        return;
    }
    int warp = threadIdx.x >> 5, lane = threadIdx.x & 31;
    int gid = b * 8 + warp;
    float s;
    if (gid < 16384) {
        int t = gid >> 12, row = gid & 4095;
        int j0 = (row & ~7) + (((row & 7) == 0) ? 1 : 0);
        uint2 xh = ((const uint2*)&g_nb_h[t][row][0])[lane];
        uint2 xl = ((const uint2*)&g_nb_l[t][row][0])[lane];
        uint2 yh = ((const uint2*)&g_nb_h[t][j0][0])[lane];
        uint2 yl = ((const uint2*)&g_nb_l[t][j0][0])[lane];
        float4 x = bf4(xh, xl), y = bf4(yh, yl);
        s = x.x*y.x + x.y*y.y + x.z*y.z + x.w*y.w;
    } else {
        int idx = gid - 16384;
        int call = idx >> 13, p = (idx >> 10) & 7, n = idx & 1023;
        int q = n ^ 512;
        unsigned xh = ((const unsigned*)&g_zb_h[call][p][n][0])[lane];
        unsigned xl = ((const unsigned*)&g_zb_l[call][p][n][0])[lane];
        unsigned yh = ((const unsigned*)&g_zb_h[call][p][q][0])[lane];
        unsigned yl = ((const unsigned*)&g_zb_l[call][p][q][0])[lane];
        float2 a = bf2(xh, xl), bv = bf2(yh, yl);
        s = a.x*bv.x + a.y*bv.y;
    }
    #pragma unroll
    for (int o = 16; o; o >>= 1) s += __shfl_xor_sync(0xffffffffu, s, o);
    if (lane == 0) {
        if (gid < 16384) g_pos[gid] = s;
        else             g_posC[gid - 16384] = s;
    }
}

// ---------------- kernel 2: MERGED gram (r13 structure) ----------------
__global__ void __launch_bounds__(256, 2) k_gram() {
    int b = blockIdx.x;
#if USE_TC
    if (b < 256) {
        int t = b >> 6, rc = (b >> 1) & 31, cs = b & 1;
        gram_tc<128, 16, true>(&g_nb_h[t][0][0], rc * 128, cs * 2048, t * 4096, 0.0f);
    } else {
        int g = (b - 256) >> 3, rcb = (b - 256) & 7;
        gram_tc<64, 8, false>(&g_zb_h[g >> 3][g & 7][0][0],
                              rcb * 128, 0, g * 1024, 1.0f / 8192.0f);
    }
#else
    if (b < 256) {
        int t = b >> 6, rc = (b >> 1) & 31, cs = b & 1;
        gram_fb_temporal(t, rc, cs);
    } else {
        int g = (b - 256) >> 3, rcb = (b - 256) & 7;
        gram_fb_contr(g >> 3, g & 7, rcb);
    }
#endif
}

// ---------------- kernel 3: temporal finalize + output (completion counter) ----------
__global__ void k_fin_temporal(float* out) {
    int gid = blockIdx.x * 256 + threadIdx.x;
    float loss = INVT + logf(g_S[gid]) - g_pos[gid] * INVT;
    block_accum<256>(loss, 1.0f / 4096.0f);
    __syncthreads();                     // block's g_acc add issued by tid 0
    if (threadIdx.x == 0) {
        __threadfence();
        unsigned done = atomicAdd(&g_cnt, 1u);
        if (done == gridDim.x - 1) out[0] = atomicAdd(&g_acc, 0.0f);
    }
}

// ---------------- launch ----------------
extern "C" void kernel_launch(void* const* d_in, const int* in_sizes, int n_in,
                              void* d_out, int out_size) {
    (void)in_sizes; (void)n_in; (void)out_size;
    const float* t0 = (const float*)d_in[0];
    const float* t1 = (const float*)d_in[1];
    const float* t2 = (const float*)d_in[2];
    const float* t3 = (const float*)d_in[3];
    const int SMEM_G = 2048 + 3 * 128 * 128 * 2;   // 100352 -> 2 CTAs/SM
    cudaFuncSetAttribute(k_gram, cudaFuncAttributeMaxDynamicSharedMemorySize, SMEM_G);
    k_normalize<<<2048, 256>>>(t0, t1, t2, t3);
    k_pos<<<6240, 256>>>();          // positives + ortho
    k_gram<<<512, 256, SMEM_G>>>();
    k_fin_temporal<<<64, 256>>>((float*)d_out);
}

// round 16
// speedup vs baseline: 1.1197x; 1.1038x over previous
#include <cuda_runtime.h>
#include <cuda_bf16.h>
#include <math.h>
#include <stdint.h>

typedef unsigned long long ull;

#define INVT 14.285714285714286f
#define C1E  20.609928f   /* INVT * log2(e) */

#if defined(__CUDA_ARCH_FEAT_SM103_ALL) || defined(__CUDA_ARCH_FEAT_SM100_ALL) || defined(__CUDA_ARCH_SPECIFIC__)
#define USE_TC 1
#else
#define USE_TC 0
#endif

// ---------------- scratch (device globals; no allocation) ----------------
__device__ __align__(256) float g_nfull[4][4096][128];            // f32 (fallback only)
__device__ __align__(256) float g_z[4][8][1024][64];              // f32 (fallback only)
__device__ __align__(256) __nv_bfloat16 g_nb_h[4][4096][128];     // bf16 hi
__device__ __align__(256) __nv_bfloat16 g_nb_l[4][4096][128];     // bf16 lo residual (pos/ortho)
__device__ __align__(256) __nv_bfloat16 g_zb_h[4][8][1024][64];
__device__ __align__(256) __nv_bfloat16 g_zb_l[4][8][1024][64];
__device__ float g_S[4 * 4096];
__device__ float g_pos[4 * 4096];      // temporal positives (exact hi+lo)
__device__ float g_posC[32768];        // contrastive positives (exact hi+lo)
__device__ float g_acc;
__device__ unsigned g_cnt;

// ---------------- generic helpers ----------------
__device__ __forceinline__ void fma2(ull &acc, ull a, ull b) {
    asm("fma.rn.f32x2 %0, %1, %2, %0;" : "+l"(acc) : "l"(a), "l"(b));
}
__device__ __forceinline__ float ulo(ull v){ return __uint_as_float((unsigned)v); }
__device__ __forceinline__ float uhi(ull v){ return __uint_as_float((unsigned)(v >> 32)); }

__device__ __forceinline__ float4 bf4(uint2 h, uint2 l) {
    float2 h0 = __bfloat1622float2(*(__nv_bfloat162*)&h.x);
    float2 h1 = __bfloat1622float2(*(__nv_bfloat162*)&h.y);
    float2 l0 = __bfloat1622float2(*(__nv_bfloat162*)&l.x);
    float2 l1 = __bfloat1622float2(*(__nv_bfloat162*)&l.y);
    return make_float4(h0.x + l0.x, h0.y + l0.y, h1.x + l1.x, h1.y + l1.y);
}
__device__ __forceinline__ float2 bf2(unsigned h, unsigned l) {
    float2 fh = __bfloat1622float2(*(__nv_bfloat162*)&h);
    float2 fl = __bfloat1622float2(*(__nv_bfloat162*)&l);
    return make_float2(fh.x + fl.x, fh.y + fl.y);
}

template<int BLK>
__device__ __forceinline__ void block_accum(float v, float scale) {
    static __shared__ float red[BLK/32];
    #pragma unroll
    for (int o = 16; o; o >>= 1) v += __shfl_xor_sync(0xffffffffu, v, o);
    int w = threadIdx.x >> 5;
    if ((threadIdx.x & 31) == 0) red[w] = v;
    __syncthreads();
    if (threadIdx.x < 32) {
        float s = (threadIdx.x < BLK/32) ? red[threadIdx.x] : 0.0f;
        #pragma unroll
        for (int o = 16; o; o >>= 1) s += __shfl_xor_sync(0xffffffffu, s, o);
        if (threadIdx.x == 0) atomicAdd(&g_acc, s * scale);
    }
}

__device__ __forceinline__ uint32_t smem_u32(const void* p) {
    uint32_t a;
    asm("{ .reg .u64 t; cvta.to.shared.u64 t, %1; cvt.u32.u64 %0, t; }" : "=r"(a) : "l"(p));
    return a;
}

#if USE_TC
__device__ __forceinline__ bool elect_one() {
    uint32_t p;
    asm volatile("{ .reg .pred p; elect.sync _|p, 0xFFFFFFFF; selp.b32 %0, 1, 0, p; }" : "=r"(p));
    return p != 0;
}
#define MBARRIER_INIT(addr, cnt) \
    asm volatile("mbarrier.init.shared.b64 [%0], %1;" :: "r"(addr), "r"(cnt) : "memory")
#define MBARRIER_INVAL(addr) \
    asm volatile("mbarrier.inval.shared.b64 [%0];" :: "r"(addr) : "memory")
#define MBARRIER_WAIT_PARITY(addr, par) do { \
    uint32_t _m = (addr), _p = (par), _d; \
    asm volatile("{ .reg .pred p; mbarrier.try_wait.parity.acquire.cta.shared::cta.b64 p, [%1], %2; selp.b32 %0,1,0,p; }" \
        : "=r"(_d) : "r"(_m), "r"(_p) : "memory"); \
    if (!_d) { \
        asm volatile("{ .reg .pred P1; WL_%=: mbarrier.try_wait.parity.acquire.cta.shared::cta.b64 P1, [%0], %1, 0x989680; @P1 bra.uni WD_%=; bra.uni WL_%=; WD_%=: }" \
            :: "r"(_m), "r"(_p) : "memory"); \
    } } while (0)
#define TCGEN05_ALLOC(dst, n) \
    asm volatile("tcgen05.alloc.cta_group::1.sync.aligned.shared::cta.b32 [%0], %1;" :: "r"(dst), "r"(n) : "memory")
#define TCGEN05_RELINQ() \
    asm volatile("tcgen05.relinquish_alloc_permit.cta_group::1.sync.aligned;")
#define TCGEN05_DEALLOC(t, n) \
    asm volatile("tcgen05.dealloc.cta_group::1.sync.aligned.b32 %0, %1;" :: "r"(t), "r"(n))
#define TCGEN05_COMMIT(mbar) \
    asm volatile("tcgen05.commit.cta_group::1.mbarrier::arrive::one.shared::cluster.b64 [%0];" :: "r"(mbar) : "memory")
#define TCGEN05_WAIT_LD()   asm volatile("tcgen05.wait::ld.sync.aligned;" ::: "memory")
#define TCGEN05_FENCE_BEFORE() asm volatile("tcgen05.fence::before_thread_sync;" ::: "memory")
#define TCGEN05_FENCE_AFTER()  asm volatile("tcgen05.fence::after_thread_sync;" ::: "memory")
#define FENCE_PROXY() asm volatile("fence.proxy.async.shared::cta;" ::: "memory")
#define LD32X32(r, addr) \
    asm volatile("tcgen05.ld.sync.aligned.32x32b.x32.b32 " \
        "{%0,%1,%2,%3,%4,%5,%6,%7,%8,%9,%10,%11,%12,%13,%14,%15," \
        "%16,%17,%18,%19,%20,%21,%22,%23,%24,%25,%26,%27,%28,%29,%30,%31}, [%32];" \
        : "=r"((r)[0]),"=r"((r)[1]),"=r"((r)[2]),"=r"((r)[3]),"=r"((r)[4]),"=r"((r)[5]),"=r"((r)[6]),"=r"((r)[7]), \
          "=r"((r)[8]),"=r"((r)[9]),"=r"((r)[10]),"=r"((r)[11]),"=r"((r)[12]),"=r"((r)[13]),"=r"((r)[14]),"=r"((r)[15]), \
          "=r"((r)[16]),"=r"((r)[17]),"=r"((r)[18]),"=r"((r)[19]),"=r"((r)[20]),"=r"((r)[21]),"=r"((r)[22]),"=r"((r)[23]), \
          "=r"((r)[24]),"=r"((r)[25]),"=r"((r)[26]),"=r"((r)[27]),"=r"((r)[28]),"=r"((r)[29]),"=r"((r)[30]),"=r"((r)[31]) \
        : "r"(addr))

__device__ __forceinline__ uint64_t make_desc(uint32_t addr) {
    const uint64_t BASE = (2ull << 61) | (1ull << 46) | (64ull << 32) | (1ull << 16);
    return BASE | ((addr >> 4) & 0x3FFF);
}
#define IDESC_BF16 0x8200490u   // kind::f16, bf16 in, f32 acc, M=128, N=128
__device__ __forceinline__ void mma_bf16(uint32_t d, uint64_t a, uint64_t b, bool en) {
    uint32_t e = en ? 1u : 0u;
    asm volatile("{\n\t.reg .pred p;\n\tsetp.ne.u32 p, %4, 0;\n\t"
        "tcgen05.mma.cta_group::1.kind::f16 [%0], %1, %2, %3, {%5,%5,%5,%5}, p;\n\t}"
        :: "r"(d), "l"(a), "l"(b), "r"(IDESC_BF16), "r"(e), "r"(0u) : "memory");
}

// 128 rows x (NC*128) cols gram + fused NT-Xent; single-term bf16 MMA, compact SMEM
// (A + 2xB tiles), 2 CTAs/SM. Hoisted staging offsets; hoisted compare operands.
// EXACT round-13 code path (65.7us passing).
template<int KF, int NC, bool TEMPORAL>
__device__ __forceinline__ void gram_tc(const __nv_bfloat16* __restrict__ bh,
                                        int rowbase, int colbase0, int auxbase, float scale) {
    constexpr int KSTEPS = KF / 16;
    constexpr int TB = 128 * KF * 2;
    constexpr int AOFF = 2048;
    constexpr int BOFF = 2048 + TB;
    constexpr int F8 = KF / 8;          // 16B chunks per row
    constexpr int ITER = (128 * F8) / 256;
    extern __shared__ char sm[];
    uint32_t smb = smem_u32(sm);
    int tid = threadIdx.x;
    if (tid == 0) { MBARRIER_INIT(smb + 0, 1); MBARRIER_INIT(smb + 8, 1); }
    if (tid < 32) { TCGEN05_ALLOC(smb + 16, 256); TCGEN05_RELINQ(); }

    int go[ITER], so[ITER];
    #pragma unroll
    for (int s = 0; s < ITER; ++s) {
        int i = tid + s * 256;
        int r = i / F8, kq = i % F8;
        go[s] = (r * KF + kq * 8) * 2;
        int bo = ((r >> 3) + (kq >> 3) * 16) * 1024 + (r & 7) * 128 + (kq & 7) * 16;
        bo ^= (bo >> 3) & 0x70;
        so[s] = bo;
    }
    {
        const char* srcA = (const char*)(bh + (size_t)rowbase * KF);
        const char* srcB = (const char*)(bh + (size_t)colbase0 * KF);
        #pragma unroll
        for (int s = 0; s < ITER; ++s) {
            *(uint4*)(sm + AOFF + so[s]) = *(const uint4*)(srcA + go[s]);
            *(uint4*)(sm + BOFF + so[s]) = *(const uint4*)(srcB + go[s]);
        }
    }
    FENCE_PROXY();
    __syncthreads();
    uint32_t tmem; asm("ld.shared.b32 %0, [%1];" : "=r"(tmem) : "r"(smb + 16));
    uint64_t adh = make_desc(smb + AOFF);

    int half = tid >> 7, w4 = (tid >> 5) & 3, lane = tid & 31;
    int rowloc = w4 * 32 + lane;
    int row = rowbase + rowloc;
    float* Ssh = (float*)(sm + 1024);
    float S = 0.0f;

    auto epi = [&](int cp) {
        MBARRIER_WAIT_PARITY(smb + 8u * (cp & 1), (cp >> 1) & 1);
        TCGEN05_FENCE_AFTER();
        if (TEMPORAL) {
            uint32_t r0[32], r1[32];
            LD32X32(r0, tmem + (uint32_t)(cp & 1) * 128 + half * 64);
            LD32X32(r1, tmem + (uint32_t)(cp & 1) * 128 + half * 64 + 32);
            TCGEN05_WAIT_LD();
            int rj0 = row - (colbase0 + cp * 128 + half * 64);
            int rj1 = rj0 - 32;
            #pragma unroll
            for (int j = 0; j < 32; ++j) {
                float d0 = __uint_as_float(r0[j]);
                float d1 = __uint_as_float(r1[j]);
                float e0, e1;
                asm("ex2.approx.f32 %0, %1;" : "=f"(e0) : "f"(fmaf(d0, C1E, -C1E)));
                asm("ex2.approx.f32 %0, %1;" : "=f"(e1) : "f"(fmaf(d1, C1E, -C1E)));
                if (j != rj0) S += e0;
                if (j != rj1) S += e1;
            }
        } else {
            #pragma unroll
            for (int g = 0; g < 2; ++g) {
                uint32_t r[32];
                LD32X32(r, tmem + (uint32_t)(cp & 1) * 128 + half * 64 + g * 32);
                TCGEN05_WAIT_LD();
                int rj = row - (colbase0 + cp * 128 + half * 64 + g * 32);
                #pragma unroll
                for (int j = 0; j < 32; ++j) {
                    float d = __uint_as_float(r[j]);
                    float e;
                    asm("ex2.approx.f32 %0, %1;" : "=f"(e) : "f"(fmaf(d, C1E, -C1E)));
                    if (j != rj) S += e;
                }
            }
        }
        TCGEN05_FENCE_BEFORE();
    };

    for (int c = 0; c < NC; ++c) {
        if (c) __syncthreads();
        if (tid < 32) {
            TCGEN05_FENCE_AFTER();
            if (elect_one()) {
                uint64_t bdh = make_desc(smb + BOFF + (uint32_t)(c & 1) * TB);
                uint32_t dt = tmem + (uint32_t)(c & 1) * 128;
                #pragma unroll
                for (int k = 0; k < KSTEPS; ++k) {
                    uint64_t off = (KF == 128) ? (uint64_t)((k >> 2) * 1024 + (k & 3) * 2)
                                               : (uint64_t)(k * 2);
                    mma_bf16(dt, adh + off, bdh + off, k > 0);
                }
                TCGEN05_COMMIT(smb + 8u * (c & 1));
            }
        }
        if (c >= 1) epi(c - 1);
        if (c + 1 < NC) {
            char* dst = sm + BOFF + (uint32_t)((c + 1) & 1) * TB;
            const char* src = (const char*)(bh + (size_t)(colbase0 + (c + 1) * 128) * KF);
            #pragma unroll
            for (int s = 0; s < ITER; ++s)
                *(uint4*)(dst + so[s]) = *(const uint4*)(src + go[s]);
            FENCE_PROXY();
        }
    }
    epi(NC - 1);

    if (TEMPORAL) {
        atomicAdd(&g_S[auxbase + row], S);
    } else {
        __syncthreads();
        if (half) Ssh[rowloc] = S;
        __syncthreads();
        float loss = 0.0f;
        if (!half) loss = INVT + logf(S + Ssh[rowloc]) - g_posC[auxbase + row] * INVT;
        block_accum<256>(loss, scale);
    }
    __syncthreads();
    if (tid == 0) { MBARRIER_INVAL(smb + 0); MBARRIER_INVAL(smb + 8); }
    if (tid < 32) TCGEN05_DEALLOC(tmem, 256);
}
#endif // USE_TC

// ---------------- fallback gram device functions (compile-only on this target) --------
#if !USE_TC
#define PT 96
#define PC 68
__device__ void gram_fb_temporal(int t, int rc, int cs) {
    extern __shared__ char smc[];
    float* Ash = (float*)smc;
    float* Bsh = (float*)smc + 128 * PT;
    int tid = threadIdx.x, tx = tid & 15, ty = tid >> 4;
    int rowbase = rc * 128, colbase0 = cs * 2048;
    const float* base = &g_nfull[t][0][0];
    for (int i = tid; i < 128 * 32; i += 256) {
        int r = i >> 5, kq = i & 31;
        ((float4*)(Ash + r * PT))[kq] = ((const float4*)(base + (size_t)(rowbase + r) * 128))[kq];
    }
    float s_acc[8];
    #pragma unroll
    for (int i = 0; i < 8; i++) s_acc[i] = 0.0f;
    for (int cc = 0; cc < 16; cc++) {
        int colbase = colbase0 + cc * 128;
        __syncthreads();
        for (int i = tid; i < 128 * 32; i += 256) {
            int c = i >> 5, kq = i & 31;
            ((float4*)(Bsh + c * PT))[kq] = ((const float4*)(base + (size_t)(colbase + c) * 128))[kq];
        }
        __syncthreads();
        ull acc[8][8];
        #pragma unroll
        for (int i = 0; i < 8; i++)
            #pragma unroll
            for (int j = 0; j < 8; j++) acc[i][j] = 0ull;
        #pragma unroll 2
        for (int k4 = 0; k4 < 32; k4++) {
            ulonglong2 af[8], bf[8];
            #pragma unroll
            for (int i = 0; i < 8; i++)
                af[i] = *(const ulonglong2*)(Ash + (ty + 16*i) * PT + 4*k4);
            #pragma unroll
            for (int j = 0; j < 8; j++)
                bf[j] = *(const ulonglong2*)(Bsh + (tx + 16*j) * PT + 4*k4);
            #pragma unroll
            for (int i = 0; i < 8; i++)
                #pragma unroll
                for (int j = 0; j < 8; j++) {
                    fma2(acc[i][j], af[i].x, bf[j].x);
                    fma2(acc[i][j], af[i].y, bf[j].y);
                }
        }
        #pragma unroll
        for (int i = 0; i < 8; i++) {
            int r = rowbase + ty + 16*i;
            #pragma unroll
            for (int j = 0; j < 8; j++) {
                int c = colbase + tx + 16*j;
                float d = ulo(acc[i][j]) + uhi(acc[i][j]);
                float e = __expf((d - 1.0f) * INVT);
                if (c != r) s_acc[i] += e;
            }
        }
    }
    #pragma unroll
    for (int i = 0; i < 8; i++) {
        float v = s_acc[i];
        v += __shfl_xor_sync(0xffffffffu, v, 1);
        v += __shfl_xor_sync(0xffffffffu, v, 2);
        v += __shfl_xor_sync(0xffffffffu, v, 4);
        v += __shfl_xor_sync(0xffffffffu, v, 8);
        if (tx == 0) atomicAdd(&g_S[t * 4096 + rowbase + ty + 16*i], v);
    }
}
__device__ void gram_fb_contr(int call, int p, int rcb) {
    extern __shared__ char smc[];
    float* Ash = (float*)smc;
    float* Bsh = (float*)smc + 128 * PC;
    int tid = threadIdx.x, tx = tid & 15, ty = tid >> 4;
    int rowbase = rcb * 128;
    int auxbase = (call * 8 + p) * 1024;
    const float* base = &g_z[call][p][0][0];
    for (int i = tid; i < 128 * 16; i += 256) {
        int r = i >> 4, kq = i & 15;
        ((float4*)(Ash + r * PC))[kq] = ((const float4*)(base + (size_t)(rowbase + r) * 64))[kq];
    }
    float s_acc[8];
    #pragma unroll
    for (int i = 0; i < 8; i++) s_acc[i] = 0.0f;
    for (int cc = 0; cc < 8; cc++) {
        int colbase = cc * 128;
        __syncthreads();
        for (int i = tid; i < 128 * 16; i += 256) {
            int c = i >> 4, kq = i & 15;
            ((float4*)(Bsh + c * PC))[kq] = ((const float4*)(base + (size_t)(colbase + c) * 64))[kq];
        }
        __syncthreads();
        ull acc[8][8];
        #pragma unroll
        for (int i = 0; i < 8; i++)
            #pragma unroll
            for (int j = 0; j < 8; j++) acc[i][j] = 0ull;
        #pragma unroll 2
        for (int k4 = 0; k4 < 16; k4++) {
            ulonglong2 af[8], bf[8];
            #pragma unroll
            for (int i = 0; i < 8; i++)
                af[i] = *(const ulonglong2*)(Ash + (ty + 16*i) * PC + 4*k4);
            #pragma unroll
            for (int j = 0; j < 8; j++)
                bf[j] = *(const ulonglong2*)(Bsh + (tx + 16*j) * PC + 4*k4);
            #pragma unroll
            for (int i = 0; i < 8; i++)
                #pragma unroll
                for (int j = 0; j < 8; j++) {
                    fma2(acc[i][j], af[i].x, bf[j].x);
                    fma2(acc[i][j], af[i].y, bf[j].y);
                }
        }
        #pragma unroll
        for (int i = 0; i < 8; i++) {
            int r = rowbase + ty + 16*i;
            #pragma unroll
            for (int j = 0; j < 8; j++) {
                int c = colbase + tx + 16*j;
                float d = ulo(acc[i][j]) + uhi(acc[i][j]);
                float e = __expf((d - 1.0f) * INVT);
                if (c != r) s_acc[i] += e;
            }
        }
    }
    __syncthreads();
    float loss = 0.0f;
    #pragma unroll
    for (int i = 0; i < 8; i++) {
        float v = s_acc[i];
        v += __shfl_xor_sync(0xffffffffu, v, 1);
        v += __shfl_xor_sync(0xffffffffu, v, 2);
        v += __shfl_xor_sync(0xffffffffu, v, 4);
        v += __shfl_xor_sync(0xffffffffu, v, 8);
        if (tx == 0) loss += INVT + logf(v) - g_posC[auxbase + rowbase + ty + 16*i] * INVT;
    }
    block_accum<256>(loss, 1.0f / 8192.0f);
}
#endif // !USE_TC

// ---------------- kernel 1: normalize + scatter (split-bf16) ----------------
__global__ void k_normalize(const float* __restrict__ t0, const float* __restrict__ t1,
                            const float* __restrict__ t2, const float* __restrict__ t3) {
    int gid = blockIdx.x * 256 + threadIdx.x;
    if (gid < 16384) g_S[gid] = 0.0f;
    if (gid == 0) { g_acc = 0.0f; g_cnt = 0u; }
    int warp = threadIdx.x >> 5, lane = threadIdx.x & 31;
    int gr = blockIdx.x * 8 + warp;
    int t = gr >> 12, r = gr & 4095;
    const float* src = (t == 0) ? t0 : (t == 1) ? t1 : (t == 2) ? t2 : t3;
    float4 v = ((const float4*)(src + (size_t)r * 128))[lane];
    float h = v.x*v.x + v.y*v.y + v.z*v.z + v.w*v.w;
    h += __shfl_xor_sync(0xffffffffu, h, 1);
    h += __shfl_xor_sync(0xffffffffu, h, 2);
    h += __shfl_xor_sync(0xffffffffu, h, 4);
    h += __shfl_xor_sync(0xffffffffu, h, 8);
    float full = h + __shfl_xor_sync(0xffffffffu, h, 16);
    float invh = 1.0f / fmaxf(sqrtf(h),    1e-8f);
    float invf = 1.0f / fmaxf(sqrtf(full), 1e-8f);

    float4 fv = make_float4(v.x*invf, v.y*invf, v.z*invf, v.w*invf);
    float4 hv = make_float4(v.x*invh, v.y*invh, v.z*invh, v.w*invh);
#if !USE_TC
    ((float4*)(&g_nfull[t][r][0]))[lane] = fv;
#endif
    __nv_bfloat16 fh[4], fl[4], hh[4], hl[4];
    float* fp = &fv.x; float* hp = &hv.x;
    #pragma unroll
    for (int i = 0; i < 4; i++) {
        fh[i] = __float2bfloat16(fp[i]);
        fl[i] = __float2bfloat16(fp[i] - __bfloat162float(fh[i]));
        hh[i] = __float2bfloat16(hp[i]);
        hl[i] = __float2bfloat16(hp[i] - __bfloat162float(hh[i]));
    }
    ((uint2*)(&g_nb_h[t][r][0]))[lane] = *(uint2*)fh;
    ((uint2*)(&g_nb_l[t][r][0]))[lane] = *(uint2*)fl;
    int n = r >> 3, p = r & 7;
    int call, off;
    if (lane < 16) { call = (t & 1) ? 1 : 0; off = (t >= 2) ? 512 : 0; }
    else           { call = (t < 2) ? 2 : 3; off = (t & 1) ? 512 : 0; }
    int li = (lane & 15);
#if !USE_TC
    ((float4*)(&g_z[call][p][n + off][0]))[li] = hv;
#endif
    ((uint2*)(&g_zb_h[call][p][n + off][0]))[li] = *(uint2*)hh;
    ((uint2*)(&g_zb_l[call][p][n + off][0]))[li] = *(uint2*)hl;
}

// ---------------- kernel 1b: exact positives (f32 from hi+lo) ----------------
__global__ void k_pos() {
    int warp = threadIdx.x >> 5, lane = threadIdx.x & 31;
    int gid = blockIdx.x * 8 + warp;
    float s;
    if (gid < 16384) {
        int t = gid >> 12, row = gid & 4095;
        int j0 = (row & ~7) + (((row & 7) == 0) ? 1 : 0);
        uint2 xh = ((const uint2*)&g_nb_h[t][row][0])[lane];
        uint2 xl = ((const uint2*)&g_nb_l[t][row][0])[lane];
        uint2 yh = ((const uint2*)&g_nb_h[t][j0][0])[lane];
        uint2 yl = ((const uint2*)&g_nb_l[t][j0][0])[lane];
        float4 x = bf4(xh, xl), y = bf4(yh, yl);
        s = x.x*y.x + x.y*y.y + x.z*y.z + x.w*y.w;
    } else {
        int idx = gid - 16384;
        int call = idx >> 13, p = (idx >> 10) & 7, n = idx & 1023;
        int q = n ^ 512;
        unsigned xh = ((const unsigned*)&g_zb_h[call][p][n][0])[lane];
        unsigned xl = ((const unsigned*)&g_zb_l[call][p][n][0])[lane];
        unsigned yh = ((const unsigned*)&g_zb_h[call][p][q][0])[lane];
        unsigned yl = ((const unsigned*)&g_zb_l[call][p][q][0])[lane];
        float2 a = bf2(xh, xl), bv = bf2(yh, yl);
        s = a.x*bv.x + a.y*bv.y;
    }
    #pragma unroll
    for (int o = 16; o; o >>= 1) s += __shfl_xor_sync(0xffffffffu, s, o);
    if (lane == 0) {
        if (gid < 16384) g_pos[gid] = s;
        else             g_posC[gid - 16384] = s;
    }
}

// ---------------- kernel 2: ortho (hi+lo reconstruction) ----------------
__global__ void k_ortho() {
    const int ca[6] = {0,0,1,1,2,2}, oa[6] = {0,512,0,512,0,512};
    const int cb[6] = {2,3,2,3,3,3}, ob[6] = {0,0,512,512,0,512};
    int pair = blockIdx.x >> 4;
    int r = (blockIdx.x & 15) * 256 + threadIdx.x;
    int n = r >> 3, p = r & 7;
    float s = 0.0f;
#if USE_TC
    const unsigned* ah = (const unsigned*)(&g_zb_h[ca[pair]][p][n + oa[pair]][0]);
    const unsigned* al = (const unsigned*)(&g_zb_l[ca[pair]][p][n + oa[pair]][0]);
    const unsigned* bh = (const unsigned*)(&g_zb_h[cb[pair]][p][n + ob[pair]][0]);
    const unsigned* bl = (const unsigned*)(&g_zb_l[cb[pair]][p][n + ob[pair]][0]);
    #pragma unroll
    for (int k = 0; k < 32; k++) {
        float2 fa = bf2(ah[k], al[k]);
        float2 fb = bf2(bh[k], bl[k]);
        s += fa.x * fb.x + fa.y * fb.y;
    }
#else
    const float4* a = (const float4*)(&g_z[ca[pair]][p][n + oa[pair]][0]);
    const float4* b = (const float4*)(&g_z[cb[pair]][p][n + ob[pair]][0]);
    #pragma unroll
    for (int k = 0; k < 16; k++) {
        float4 fa = a[k], fb = b[k];
        s += fa.x*fb.x + fa.y*fb.y + fa.z*fb.z + fa.w*fb.w;
    }
#endif
    block_accum<256>(fmaxf(s, 0.0f), 1.0f / 4096.0f);
}

// ---------------- kernel 3: MERGED gram (blocks 0-255 temporal, 256-511 contrastive) --
__global__ void __launch_bounds__(256, 2) k_gram() {
    int b = blockIdx.x;
#if USE_TC
    if (b < 256) {
        int t = b >> 6, rc = (b >> 1) & 31, cs = b & 1;
        gram_tc<128, 16, true>(&g_nb_h[t][0][0], rc * 128, cs * 2048, t * 4096, 0.0f);
    } else {
        int g = (b - 256) >> 3, rcb = (b - 256) & 7;
        gram_tc<64, 8, false>(&g_zb_h[g >> 3][g & 7][0][0],
                              rcb * 128, 0, g * 1024, 1.0f / 8192.0f);
    }
#else
    if (b < 256) {
        int t = b >> 6, rc = (b >> 1) & 31, cs = b & 1;
        gram_fb_temporal(t, rc, cs);
    } else {
        int g = (b - 256) >> 3, rcb = (b - 256) & 7;
        gram_fb_contr(g >> 3, g & 7, rcb);
    }
#endif
}

// ---------------- kernel 4: temporal finalize + output (completion counter) ----------
__global__ void k_fin_temporal(float* out) {
    int gid = blockIdx.x * 256 + threadIdx.x;
    float loss = INVT + logf(g_S[gid]) - g_pos[gid] * INVT;
    block_accum<256>(loss, 1.0f / 4096.0f);
    __syncthreads();                     // block's g_acc add issued by tid 0
    if (threadIdx.x == 0) {
        __threadfence();
        unsigned done = atomicAdd(&g_cnt, 1u);
        if (done == gridDim.x - 1) out[0] = atomicAdd(&g_acc, 0.0f);
    }
}

// ---------------- launch ----------------
extern "C" void kernel_launch(void* const* d_in, const int* in_sizes, int n_in,
                              void* d_out, int out_size) {
    (void)in_sizes; (void)n_in; (void)out_size;
    const float* t0 = (const float*)d_in[0];
    const float* t1 = (const float*)d_in[1];
    const float* t2 = (const float*)d_in[2];
    const float* t3 = (const float*)d_in[3];
    const int SMEM_G = 2048 + 3 * 128 * 128 * 2;   // 100352 -> 2 CTAs/SM
    cudaFuncSetAttribute(k_gram, cudaFuncAttributeMaxDynamicSharedMemorySize, SMEM_G);
    k_normalize<<<2048, 256>>>(t0, t1, t2, t3);
    k_pos<<<6144, 256>>>();
    k_ortho<<<96, 256>>>();
    k_gram<<<512, 256, SMEM_G>>>();
    k_fin_temporal<<<64, 256>>>((float*)d_out);
}

// round 17
// speedup vs baseline: 1.1741x; 1.0486x over previous
#include <cuda_runtime.h>
#include <cuda_bf16.h>
#include <math.h>
#include <stdint.h>

typedef unsigned long long ull;

#define INVT 14.285714285714286f
#define C1E  20.609928f   /* INVT * log2(e) */

#if defined(__CUDA_ARCH_FEAT_SM103_ALL) || defined(__CUDA_ARCH_FEAT_SM100_ALL) || defined(__CUDA_ARCH_SPECIFIC__)
#define USE_TC 1
#else
#define USE_TC 0
#endif

// ---------------- scratch (device globals; no allocation) ----------------
__device__ __align__(256) float g_nfull[4][4096][128];            // f32 (fallback only)
__device__ __align__(256) float g_z[4][8][1024][64];              // f32 (fallback only)
__device__ __align__(256) __nv_bfloat16 g_nb_h[4][4096][128];     // bf16 hi
__device__ __align__(256) __nv_bfloat16 g_nb_l[4][4096][128];     // bf16 lo residual (pos/ortho)
__device__ __align__(256) __nv_bfloat16 g_zb_h[4][8][1024][64];
__device__ __align__(256) __nv_bfloat16 g_zb_l[4][8][1024][64];
__device__ float g_S[4 * 4096];        // temporal row sums (atomic)
__device__ float g_SC[32768];          // contrastive row sums (plain store)
__device__ float g_pos[4 * 4096];      // temporal positives (exact hi+lo)
__device__ float g_posC[32768];        // contrastive positives (exact hi+lo)
__device__ float g_acc;
__device__ unsigned g_cnt;

// ---------------- generic helpers ----------------
__device__ __forceinline__ void fma2(ull &acc, ull a, ull b) {
    asm("fma.rn.f32x2 %0, %1, %2, %0;" : "+l"(acc) : "l"(a), "l"(b));
}
__device__ __forceinline__ float ulo(ull v){ return __uint_as_float((unsigned)v); }
__device__ __forceinline__ float uhi(ull v){ return __uint_as_float((unsigned)(v >> 32)); }

__device__ __forceinline__ float4 bf4(uint2 h, uint2 l) {
    float2 h0 = __bfloat1622float2(*(__nv_bfloat162*)&h.x);
    float2 h1 = __bfloat1622float2(*(__nv_bfloat162*)&h.y);
    float2 l0 = __bfloat1622float2(*(__nv_bfloat162*)&l.x);
    float2 l1 = __bfloat1622float2(*(__nv_bfloat162*)&l.y);
    return make_float4(h0.x + l0.x, h0.y + l0.y, h1.x + l1.x, h1.y + l1.y);
}
__device__ __forceinline__ float2 bf2(unsigned h, unsigned l) {
    float2 fh = __bfloat1622float2(*(__nv_bfloat162*)&h);
    float2 fl = __bfloat1622float2(*(__nv_bfloat162*)&l);
    return make_float2(fh.x + fl.x, fh.y + fl.y);
}

template<int BLK>
__device__ __forceinline__ void block_accum(float v, float scale) {
    static __shared__ float red[BLK/32];
    #pragma unroll
    for (int o = 16; o; o >>= 1) v += __shfl_xor_sync(0xffffffffu, v, o);
    int w = threadIdx.x >> 5;
    if ((threadIdx.x & 31) == 0) red[w] = v;
    __syncthreads();
    if (threadIdx.x < 32) {
        float s = (threadIdx.x < BLK/32) ? red[threadIdx.x] : 0.0f;
        #pragma unroll
        for (int o = 16; o; o >>= 1) s += __shfl_xor_sync(0xffffffffu, s, o);
        if (threadIdx.x == 0) atomicAdd(&g_acc, s * scale);
    }
}

__device__ __forceinline__ uint32_t smem_u32(const void* p) {
    uint32_t a;
    asm("{ .reg .u64 t; cvta.to.shared.u64 t, %1; cvt.u32.u64 %0, t; }" : "=r"(a) : "l"(p));
    return a;
}

#if USE_TC
__device__ __forceinline__ bool elect_one() {
    uint32_t p;
    asm volatile("{ .reg .pred p; elect.sync _|p, 0xFFFFFFFF; selp.b32 %0, 1, 0, p; }" : "=r"(p));
    return p != 0;
}
#define MBARRIER_INIT(addr, cnt) \
    asm volatile("mbarrier.init.shared.b64 [%0], %1;" :: "r"(addr), "r"(cnt) : "memory")
#define MBARRIER_INVAL(addr) \
    asm volatile("mbarrier.inval.shared.b64 [%0];" :: "r"(addr) : "memory")
#define MBARRIER_WAIT_PARITY(addr, par) do { \
    uint32_t _m = (addr), _p = (par), _d; \
    asm volatile("{ .reg .pred p; mbarrier.try_wait.parity.acquire.cta.shared::cta.b64 p, [%1], %2; selp.b32 %0,1,0,p; }" \
        : "=r"(_d) : "r"(_m), "r"(_p) : "memory"); \
    if (!_d) { \
        asm volatile("{ .reg .pred P1; WL_%=: mbarrier.try_wait.parity.acquire.cta.shared::cta.b64 P1, [%0], %1, 0x989680; @P1 bra.uni WD_%=; bra.uni WL_%=; WD_%=: }" \
            :: "r"(_m), "r"(_p) : "memory"); \
    } } while (0)
#define TCGEN05_ALLOC(dst, n) \
    asm volatile("tcgen05.alloc.cta_group::1.sync.aligned.shared::cta.b32 [%0], %1;" :: "r"(dst), "r"(n) : "memory")
#define TCGEN05_RELINQ() \
    asm volatile("tcgen05.relinquish_alloc_permit.cta_group::1.sync.aligned;")
#define TCGEN05_DEALLOC(t, n) \
    asm volatile("tcgen05.dealloc.cta_group::1.sync.aligned.b32 %0, %1;" :: "r"(t), "r"(n))
#define TCGEN05_COMMIT(mbar) \
    asm volatile("tcgen05.commit.cta_group::1.mbarrier::arrive::one.shared::cluster.b64 [%0];" :: "r"(mbar) : "memory")
#define TCGEN05_WAIT_LD()   asm volatile("tcgen05.wait::ld.sync.aligned;" ::: "memory")
#define TCGEN05_FENCE_BEFORE() asm volatile("tcgen05.fence::before_thread_sync;" ::: "memory")
#define TCGEN05_FENCE_AFTER()  asm volatile("tcgen05.fence::after_thread_sync;" ::: "memory")
#define FENCE_PROXY() asm volatile("fence.proxy.async.shared::cta;" ::: "memory")
#define LD32X32(r, addr) \
    asm volatile("tcgen05.ld.sync.aligned.32x32b.x32.b32 " \
        "{%0,%1,%2,%3,%4,%5,%6,%7,%8,%9,%10,%11,%12,%13,%14,%15," \
        "%16,%17,%18,%19,%20,%21,%22,%23,%24,%25,%26,%27,%28,%29,%30,%31}, [%32];" \
        : "=r"((r)[0]),"=r"((r)[1]),"=r"((r)[2]),"=r"((r)[3]),"=r"((r)[4]),"=r"((r)[5]),"=r"((r)[6]),"=r"((r)[7]), \
          "=r"((r)[8]),"=r"((r)[9]),"=r"((r)[10]),"=r"((r)[11]),"=r"((r)[12]),"=r"((r)[13]),"=r"((r)[14]),"=r"((r)[15]), \
          "=r"((r)[16]),"=r"((r)[17]),"=r"((r)[18]),"=r"((r)[19]),"=r"((r)[20]),"=r"((r)[21]),"=r"((r)[22]),"=r"((r)[23]), \
          "=r"((r)[24]),"=r"((r)[25]),"=r"((r)[26]),"=r"((r)[27]),"=r"((r)[28]),"=r"((r)[29]),"=r"((r)[30]),"=r"((r)[31]) \
        : "r"(addr))

__device__ __forceinline__ uint64_t make_desc(uint32_t addr) {
    const uint64_t BASE = (2ull << 61) | (1ull << 46) | (64ull << 32) | (1ull << 16);
    return BASE | ((addr >> 4) & 0x3FFF);
}
#define IDESC_BF16 0x8200490u   // kind::f16, bf16 in, f32 acc, M=128, N=128
__device__ __forceinline__ void mma_bf16(uint32_t d, uint64_t a, uint64_t b, bool en) {
    uint32_t e = en ? 1u : 0u;
    asm volatile("{\n\t.reg .pred p;\n\tsetp.ne.u32 p, %4, 0;\n\t"
        "tcgen05.mma.cta_group::1.kind::f16 [%0], %1, %2, %3, {%5,%5,%5,%5}, p;\n\t}"
        :: "r"(d), "l"(a), "l"(b), "r"(IDESC_BF16), "r"(e), "r"(0u) : "memory");
}

// 128 rows x (NC*128) cols gram; single-term bf16 MMA, compact SMEM (A + 2xB),
// 2 CTAs/SM, hoisted staging offsets, hoisted compare operands. Round-13 data path;
// contrastive result plain-stored to g_SC (loss deferred to k_fin -> no g_posC read).
template<int KF, int NC, bool TEMPORAL>
__device__ __forceinline__ void gram_tc(const __nv_bfloat16* __restrict__ bh,
                                        int rowbase, int colbase0, int auxbase) {
    constexpr int KSTEPS = KF / 16;
    constexpr int TB = 128 * KF * 2;
    constexpr int AOFF = 2048;
    constexpr int BOFF = 2048 + TB;
    constexpr int F8 = KF / 8;          // 16B chunks per row
    constexpr int ITER = (128 * F8) / 256;
    extern __shared__ char sm[];
    uint32_t smb = smem_u32(sm);
    int tid = threadIdx.x;
    if (tid == 0) { MBARRIER_INIT(smb + 0, 1); MBARRIER_INIT(smb + 8, 1); }
    if (tid < 32) { TCGEN05_ALLOC(smb + 16, 256); TCGEN05_RELINQ(); }

    int go[ITER], so[ITER];
    #pragma unroll
    for (int s = 0; s < ITER; ++s) {
        int i = tid + s * 256;
        int r = i / F8, kq = i % F8;
        go[s] = (r * KF + kq * 8) * 2;
        int bo = ((r >> 3) + (kq >> 3) * 16) * 1024 + (r & 7) * 128 + (kq & 7) * 16;
        bo ^= (bo >> 3) & 0x70;
        so[s] = bo;
    }
    {
        const char* srcA = (const char*)(bh + (size_t)rowbase * KF);
        const char* srcB = (const char*)(bh + (size_t)colbase0 * KF);
        #pragma unroll
        for (int s = 0; s < ITER; ++s) {
            *(uint4*)(sm + AOFF + so[s]) = *(const uint4*)(srcA + go[s]);
            *(uint4*)(sm + BOFF + so[s]) = *(const uint4*)(srcB + go[s]);
        }
    }
    FENCE_PROXY();
    __syncthreads();
    uint32_t tmem; asm("ld.shared.b32 %0, [%1];" : "=r"(tmem) : "r"(smb + 16));
    uint64_t adh = make_desc(smb + AOFF);

    int half = tid >> 7, w4 = (tid >> 5) & 3, lane = tid & 31;
    int rowloc = w4 * 32 + lane;
    int row = rowbase + rowloc;
    float* Ssh = (float*)(sm + 1024);
    float S = 0.0f;

    auto epi = [&](int cp) {
        MBARRIER_WAIT_PARITY(smb + 8u * (cp & 1), (cp >> 1) & 1);
        TCGEN05_FENCE_AFTER();
        if (TEMPORAL) {
            uint32_t r0[32], r1[32];
            LD32X32(r0, tmem + (uint32_t)(cp & 1) * 128 + half * 64);
            LD32X32(r1, tmem + (uint32_t)(cp & 1) * 128 + half * 64 + 32);
            TCGEN05_WAIT_LD();
            int rj0 = row - (colbase0 + cp * 128 + half * 64);
            int rj1 = rj0 - 32;
            #pragma unroll
            for (int j = 0; j < 32; ++j) {
                float d0 = __uint_as_float(r0[j]);
                float d1 = __uint_as_float(r1[j]);
                float e0, e1;
                asm("ex2.approx.f32 %0, %1;" : "=f"(e0) : "f"(fmaf(d0, C1E, -C1E)));
                asm("ex2.approx.f32 %0, %1;" : "=f"(e1) : "f"(fmaf(d1, C1E, -C1E)));
                if (j != rj0) S += e0;
                if (j != rj1) S += e1;
            }
        } else {
            #pragma unroll
            for (int g = 0; g < 2; ++g) {
                uint32_t r[32];
                LD32X32(r, tmem + (uint32_t)(cp & 1) * 128 + half * 64 + g * 32);
                TCGEN05_WAIT_LD();
                int rj = row - (colbase0 + cp * 128 + half * 64 + g * 32);
                #pragma unroll
                for (int j = 0; j < 32; ++j) {
                    float d = __uint_as_float(r[j]);
                    float e;
                    asm("ex2.approx.f32 %0, %1;" : "=f"(e) : "f"(fmaf(d, C1E, -C1E)));
                    if (j != rj) S += e;
                }
            }
        }
        TCGEN05_FENCE_BEFORE();
    };

    for (int c = 0; c < NC; ++c) {
        if (c) __syncthreads();
        if (tid < 32) {
            TCGEN05_FENCE_AFTER();
            if (elect_one()) {
                uint64_t bdh = make_desc(smb + BOFF + (uint32_t)(c & 1) * TB);
                uint32_t dt = tmem + (uint32_t)(c & 1) * 128;
                #pragma unroll
                for (int k = 0; k < KSTEPS; ++k) {
                    uint64_t off = (KF == 128) ? (uint64_t)((k >> 2) * 1024 + (k & 3) * 2)
                                               : (uint64_t)(k * 2);
                    mma_bf16(dt, adh + off, bdh + off, k > 0);
                }
                TCGEN05_COMMIT(smb + 8u * (c & 1));
            }
        }
        if (c >= 1) epi(c - 1);
        if (c + 1 < NC) {
            char* dst = sm + BOFF + (uint32_t)((c + 1) & 1) * TB;
            const char* src = (const char*)(bh + (size_t)(colbase0 + (c + 1) * 128) * KF);
            #pragma unroll
            for (int s = 0; s < ITER; ++s)
                *(uint4*)(dst + so[s]) = *(const uint4*)(src + go[s]);
            FENCE_PROXY();
        }
    }
    epi(NC - 1);

    if (TEMPORAL) {
        atomicAdd(&g_S[auxbase + row], S);
    } else {
        __syncthreads();
        if (half) Ssh[rowloc] = S;
        __syncthreads();
        if (!half) g_SC[auxbase + row] = S + Ssh[rowloc];   // loss deferred to k_fin
    }
    __syncthreads();
    if (tid == 0) { MBARRIER_INVAL(smb + 0); MBARRIER_INVAL(smb + 8); }
    if (tid < 32) TCGEN05_DEALLOC(tmem, 256);
}
#endif // USE_TC

// ---------------- fallback gram device functions (compile-only on this target) --------
#if !USE_TC
#define PT 96
#define PC 68
__device__ void gram_fb_temporal(int t, int rc, int cs) {
    extern __shared__ char smc[];
    float* Ash = (float*)smc;
    float* Bsh = (float*)smc + 128 * PT;
    int tid = threadIdx.x, tx = tid & 15, ty = tid >> 4;
    int rowbase = rc * 128, colbase0 = cs * 2048;
    const float* base = &g_nfull[t][0][0];
    for (int i = tid; i < 128 * 32; i += 256) {
        int r = i >> 5, kq = i & 31;
        ((float4*)(Ash + r * PT))[kq] = ((const float4*)(base + (size_t)(rowbase + r) * 128))[kq];
    }
    float s_acc[8];
    #pragma unroll
    for (int i = 0; i < 8; i++) s_acc[i] = 0.0f;
    for (int cc = 0; cc < 16; cc++) {
        int colbase = colbase0 + cc * 128;
        __syncthreads();
        for (int i = tid; i < 128 * 32; i += 256) {
            int c = i >> 5, kq = i & 31;
            ((float4*)(Bsh + c * PT))[kq] = ((const float4*)(base + (size_t)(colbase + c) * 128))[kq];
        }
        __syncthreads();
        ull acc[8][8];
        #pragma unroll
        for (int i = 0; i < 8; i++)
            #pragma unroll
            for (int j = 0; j < 8; j++) acc[i][j] = 0ull;
        #pragma unroll 2
        for (int k4 = 0; k4 < 32; k4++) {
            ulonglong2 af[8], bf[8];
            #pragma unroll
            for (int i = 0; i < 8; i++)
                af[i] = *(const ulonglong2*)(Ash + (ty + 16*i) * PT + 4*k4);
            #pragma unroll
            for (int j = 0; j < 8; j++)
                bf[j] = *(const ulonglong2*)(Bsh + (tx + 16*j) * PT + 4*k4);
            #pragma unroll
            for (int i = 0; i < 8; i++)
                #pragma unroll
                for (int j = 0; j < 8; j++) {
                    fma2(acc[i][j], af[i].x, bf[j].x);
                    fma2(acc[i][j], af[i].y, bf[j].y);
                }
        }
        #pragma unroll
        for (int i = 0; i < 8; i++) {
            int r = rowbase + ty + 16*i;
            #pragma unroll
            for (int j = 0; j < 8; j++) {
                int c = colbase + tx + 16*j;
                float d = ulo(acc[i][j]) + uhi(acc[i][j]);
                float e = __expf((d - 1.0f) * INVT);
                if (c != r) s_acc[i] += e;
            }
        }
    }
    #pragma unroll
    for (int i = 0; i < 8; i++) {
        float v = s_acc[i];
        v += __shfl_xor_sync(0xffffffffu, v, 1);
        v += __shfl_xor_sync(0xffffffffu, v, 2);
        v += __shfl_xor_sync(0xffffffffu, v, 4);
        v += __shfl_xor_sync(0xffffffffu, v, 8);
        if (tx == 0) atomicAdd(&g_S[t * 4096 + rowbase + ty + 16*i], v);
    }
}
__device__ void gram_fb_contr(int call, int p, int rcb) {
    extern __shared__ char smc[];
    float* Ash = (float*)smc;
    float* Bsh = (float*)smc + 128 * PC;
    int tid = threadIdx.x, tx = tid & 15, ty = tid >> 4;
    int rowbase = rcb * 128;
    int auxbase = (call * 8 + p) * 1024;
    const float* base = &g_z[call][p][0][0];
    for (int i = tid; i < 128 * 16; i += 256) {
        int r = i >> 4, kq = i & 15;
        ((float4*)(Ash + r * PC))[kq] = ((const float4*)(base + (size_t)(rowbase + r) * 64))[kq];
    }
    float s_acc[8];
    #pragma unroll
    for (int i = 0; i < 8; i++) s_acc[i] = 0.0f;
    for (int cc = 0; cc < 8; cc++) {
        int colbase = cc * 128;
        __syncthreads();
        for (int i = tid; i < 128 * 16; i += 256) {
            int c = i >> 4, kq = i & 15;
            ((float4*)(Bsh + c * PC))[kq] = ((const float4*)(base + (size_t)(colbase + c) * 64))[kq];
        }
        __syncthreads();
        ull acc[8][8];
        #pragma unroll
        for (int i = 0; i < 8; i++)
            #pragma unroll
            for (int j = 0; j < 8; j++) acc[i][j] = 0ull;
        #pragma unroll 2
        for (int k4 = 0; k4 < 16; k4++) {
            ulonglong2 af[8], bf[8];
            #pragma unroll
            for (int i = 0; i < 8; i++)
                af[i] = *(const ulonglong2*)(Ash + (ty + 16*i) * PC + 4*k4);
            #pragma unroll
            for (int j = 0; j < 8; j++)
                bf[j] = *(const ulonglong2*)(Bsh + (tx + 16*j) * PC + 4*k4);
            #pragma unroll
            for (int i = 0; i < 8; i++)
                #pragma unroll
                for (int j = 0; j < 8; j++) {
                    fma2(acc[i][j], af[i].x, bf[j].x);
                    fma2(acc[i][j], af[i].y, bf[j].y);
                }
        }
        #pragma unroll
        for (int i = 0; i < 8; i++) {
            int r = rowbase + ty + 16*i;
            #pragma unroll
            for (int j = 0; j < 8; j++) {
                int c = colbase + tx + 16*j;
                float d = ulo(acc[i][j]) + uhi(acc[i][j]);
                float e = __expf((d - 1.0f) * INVT);
                if (c != r) s_acc[i] += e;
            }
        }
    }
    #pragma unroll
    for (int i = 0; i < 8; i++) {
        float v = s_acc[i];
        v += __shfl_xor_sync(0xffffffffu, v, 1);
        v += __shfl_xor_sync(0xffffffffu, v, 2);
        v += __shfl_xor_sync(0xffffffffu, v, 4);
        v += __shfl_xor_sync(0xffffffffu, v, 8);
        if (tx == 0) g_SC[auxbase + rowbase + ty + 16*i] = v;
    }
}
#endif // !USE_TC

// ---------------- kernel 1: normalize + scatter (split-bf16) ----------------
__global__ void k_normalize(const float* __restrict__ t0, const float* __restrict__ t1,
                            const float* __restrict__ t2, const float* __restrict__ t3) {
    int gid = blockIdx.x * 256 + threadIdx.x;
    if (gid < 16384) g_S[gid] = 0.0f;
    if (gid == 0) { g_acc = 0.0f; g_cnt = 0u; }
    int warp = threadIdx.x >> 5, lane = threadIdx.x & 31;
    int gr = blockIdx.x * 8 + warp;
    int t = gr >> 12, r = gr & 4095;
    const float* src = (t == 0) ? t0 : (t == 1) ? t1 : (t == 2) ? t2 : t3;
    float4 v = ((const float4*)(src + (size_t)r * 128))[lane];
    float h = v.x*v.x + v.y*v.y + v.z*v.z + v.w*v.w;
    h += __shfl_xor_sync(0xffffffffu, h, 1);
    h += __shfl_xor_sync(0xffffffffu, h, 2);
    h += __shfl_xor_sync(0xffffffffu, h, 4);
    h += __shfl_xor_sync(0xffffffffu, h, 8);
    float full = h + __shfl_xor_sync(0xffffffffu, h, 16);
    float invh = 1.0f / fmaxf(sqrtf(h),    1e-8f);
    float invf = 1.0f / fmaxf(sqrtf(full), 1e-8f);

    float4 fv = make_float4(v.x*invf, v.y*invf, v.z*invf, v.w*invf);
    float4 hv = make_float4(v.x*invh, v.y*invh, v.z*invh, v.w*invh);
#if !USE_TC
    ((float4*)(&g_nfull[t][r][0]))[lane] = fv;
#endif
    __nv_bfloat16 fh[4], fl[4], hh[4], hl[4];
    float* fp = &fv.x; float* hp = &hv.x;
    #pragma unroll
    for (int i = 0; i < 4; i++) {
        fh[i] = __float2bfloat16(fp[i]);
        fl[i] = __float2bfloat16(fp[i] - __bfloat162float(fh[i]));
        hh[i] = __float2bfloat16(hp[i]);
        hl[i] = __float2bfloat16(hp[i] - __bfloat162float(hh[i]));
    }
    ((uint2*)(&g_nb_h[t][r][0]))[lane] = *(uint2*)fh;
    ((uint2*)(&g_nb_l[t][r][0]))[lane] = *(uint2*)fl;
    int n = r >> 3, p = r & 7;
    int call, off;
    if (lane < 16) { call = (t & 1) ? 1 : 0; off = (t >= 2) ? 512 : 0; }
    else           { call = (t < 2) ? 2 : 3; off = (t & 1) ? 512 : 0; }
    int li = (lane & 15);
#if !USE_TC
    ((float4*)(&g_z[call][p][n + off][0]))[li] = hv;
#endif
    ((uint2*)(&g_zb_h[call][p][n + off][0]))[li] = *(uint2*)hh;
    ((uint2*)(&g_zb_l[call][p][n + off][0]))[li] = *(uint2*)hl;
}

// ---------------- kernel 1b: exact positives (f32 from hi+lo) ----------------
__global__ void k_pos() {
    int warp = threadIdx.x >> 5, lane = threadIdx.x & 31;
    int gid = blockIdx.x * 8 + warp;
    float s;
    if (gid < 16384) {
        int t = gid >> 12, row = gid & 4095;
        int j0 = (row & ~7) + (((row & 7) == 0) ? 1 : 0);
        uint2 xh = ((const uint2*)&g_nb_h[t][row][0])[lane];
        uint2 xl = ((const uint2*)&g_nb_l[t][row][0])[lane];
        uint2 yh = ((const uint2*)&g_nb_h[t][j0][0])[lane];
        uint2 yl = ((const uint2*)&g_nb_l[t][j0][0])[lane];
        float4 x = bf4(xh, xl), y = bf4(yh, yl);
        s = x.x*y.x + x.y*y.y + x.z*y.z + x.w*y.w;
    } else {
        int idx = gid - 16384;
        int call = idx >> 13, p = (idx >> 10) & 7, n = idx & 1023;
        int q = n ^ 512;
        unsigned xh = ((const unsigned*)&g_zb_h[call][p][n][0])[lane];
        unsigned xl = ((const unsigned*)&g_zb_l[call][p][n][0])[lane];
        unsigned yh = ((const unsigned*)&g_zb_h[call][p][q][0])[lane];
        unsigned yl = ((const unsigned*)&g_zb_l[call][p][q][0])[lane];
        float2 a = bf2(xh, xl), bv = bf2(yh, yl);
        s = a.x*bv.x + a.y*bv.y;
    }
    #pragma unroll
    for (int o = 16; o; o >>= 1) s += __shfl_xor_sync(0xffffffffu, s, o);
    if (lane == 0) {
        if (gid < 16384) g_pos[gid] = s;
        else             g_posC[gid - 16384] = s;
    }
}

// ---------------- kernel 2: ortho (hi+lo reconstruction) ----------------
__global__ void k_ortho() {
    const int ca[6] = {0,0,1,1,2,2}, oa[6] = {0,512,0,512,0,512};
    const int cb[6] = {2,3,2,3,3,3}, ob[6] = {0,0,512,512,0,512};
    int pair = blockIdx.x >> 4;
    int r = (blockIdx.x & 15) * 256 + threadIdx.x;
    int n = r >> 3, p = r & 7;
    float s = 0.0f;
#if USE_TC
    const unsigned* ah = (const unsigned*)(&g_zb_h[ca[pair]][p][n + oa[pair]][0]);
    const unsigned* al = (const unsigned*)(&g_zb_l[ca[pair]][p][n + oa[pair]][0]);
    const unsigned* bh = (const unsigned*)(&g_zb_h[cb[pair]][p][n + ob[pair]][0]);
    const unsigned* bl = (const unsigned*)(&g_zb_l[cb[pair]][p][n + ob[pair]][0]);
    #pragma unroll
    for (int k = 0; k < 32; k++) {
        float2 fa = bf2(ah[k], al[k]);
        float2 fb = bf2(bh[k], bl[k]);
        s += fa.x * fb.x + fa.y * fb.y;
    }
#else
    const float4* a = (const float4*)(&g_z[ca[pair]][p][n + oa[pair]][0]);
    const float4* b = (const float4*)(&g_z[cb[pair]][p][n + ob[pair]][0]);
    #pragma unroll
    for (int k = 0; k < 16; k++) {
        float4 fa = a[k], fb = b[k];
        s += fa.x*fb.x + fa.y*fb.y + fa.z*fb.z + fa.w*fb.w;
    }
#endif
    block_accum<256>(fmaxf(s, 0.0f), 1.0f / 4096.0f);
}

// ---------------- kernel 3: MERGED gram (blocks 0-255 temporal, 256-511 contrastive) --
__global__ void __launch_bounds__(256, 2) k_gram() {
    int b = blockIdx.x;
#if USE_TC
    if (b < 256) {
        int t = b >> 6, rc = (b >> 1) & 31, cs = b & 1;
        gram_tc<128, 16, true>(&g_nb_h[t][0][0], rc * 128, cs * 2048, t * 4096);
    } else {
        int g = (b - 256) >> 3, rcb = (b - 256) & 7;
        gram_tc<64, 8, false>(&g_zb_h[g >> 3][g & 7][0][0], rcb * 128, 0, g * 1024);
    }
#else
    if (b < 256) {
        int t = b >> 6, rc = (b >> 1) & 31, cs = b & 1;
        gram_fb_temporal(t, rc, cs);
    } else {
        int g = (b - 256) >> 3, rcb = (b - 256) & 7;
        gram_fb_contr(g >> 3, g & 7, rcb);
    }
#endif
}

// ---------------- kernel 4: finalize per-row losses + output (counter) ----------
__global__ void k_fin(float* out) {
    int gid = blockIdx.x * 256 + threadIdx.x;   // 0..49151
    float v;
    if (gid < 16384) {
        v = (INVT + logf(g_S[gid]) - g_pos[gid] * INVT) * (1.0f / 4096.0f);
    } else {
        int i = gid - 16384;
        v = (INVT + logf(g_SC[i]) - g_posC[i] * INVT) * (1.0f / 8192.0f);
    }
    block_accum<256>(v, 1.0f);
    __syncthreads();                     // block's g_acc add issued by tid 0
    if (threadIdx.x == 0) {
        __threadfence();
        unsigned done = atomicAdd(&g_cnt, 1u);
        if (done == gridDim.x - 1) out[0] = atomicAdd(&g_acc, 0.0f);
    }
}

// ---------------- launch (stream fork/join: pos+ortho overlap gram) ----------------
extern "C" void kernel_launch(void* const* d_in, const int* in_sizes, int n_in,
                              void* d_out, int out_size) {
    (void)in_sizes; (void)n_in; (void)out_size;
    const float* t0 = (const float*)d_in[0];
    const float* t1 = (const float*)d_in[1];
    const float* t2 = (const float*)d_in[2];
    const float* t3 = (const float*)d_in[3];
    const int SMEM_G = 2048 + 3 * 128 * 128 * 2;   // 100352 -> 2 CTAs/SM
    static cudaStream_t s1 = nullptr;
    static cudaEvent_t e0 = nullptr, e1 = nullptr;
    if (!s1) {
        cudaStreamCreateWithFlags(&s1, cudaStreamNonBlocking);
        cudaEventCreateWithFlags(&e0, cudaEventDisableTiming);
        cudaEventCreateWithFlags(&e1, cudaEventDisableTiming);
        cudaFuncSetAttribute(k_gram, cudaFuncAttributeMaxDynamicSharedMemorySize, SMEM_G);
    }
    k_normalize<<<2048, 256>>>(t0, t1, t2, t3);
    cudaEventRecord(e0, 0);
    cudaStreamWaitEvent(s1, e0, 0);
    k_pos<<<6144, 256, 0, s1>>>();
    k_ortho<<<96, 256, 0, s1>>>();
    k_gram<<<512, 256, SMEM_G>>>();
    cudaEventRecord(e1, s1);
    cudaStreamWaitEvent(0, e1, 0);
    k_fin<<<192, 256>>>((float*)d_out);
}